// round 3
// baseline (speedup 1.0000x reference)
#include <cuda_runtime.h>

#define NV 100000
#define NE 1600000
#define ZD 192
#define HD 512
#define OD 64
#define EPS 1e-5f

typedef unsigned long long ull;

__device__ __forceinline__ ull pack2(float lo, float hi){
    ull r; asm("mov.b64 %0, {%1,%2};" : "=l"(r) : "f"(lo), "f"(hi)); return r;
}
__device__ __forceinline__ void fma2(ull &d, ull a, ull b){
    asm("fma.rn.f32x2 %0, %1, %2, %0;" : "+l"(d) : "l"(a), "l"(b));
}
__device__ __forceinline__ void add2(ull &d, ull a){
    asm("add.rn.f32x2 %0, %1, %0;" : "+l"(d) : "l"(a));
}
__device__ __forceinline__ float2 unpack2(ull v){
    float2 f; asm("mov.b64 {%0,%1}, %2;" : "=f"(f.x), "=f"(f.y) : "l"(v)); return f;
}

// scratch (no allocations allowed)
__device__ int   g_deg[NV];
__device__ int   g_off[NV];
__device__ int   g_cur[NV];
__device__ int   g_csc[NE];
__device__ float g_norm[NV];
__device__ float g_tA[NV*64];
__device__ float g_tB[NV*64];
__device__ float g_H[(size_t)NV*ZD];   // [h1|h2|h3] per node
__device__ float g_S[ZD*ZD];           // Gram (upper computed, mirrored)
__device__ float g_cs[ZD];             // column sums
__device__ float g_M[HD*ZD];           // folded weights
__device__ float g_cv[HD];             // folded bias
__device__ float g_av[HD];             // q*gamma*invstd
__device__ float g_dt[HD];             // per-channel const
__device__ float g_V[ZD*OD];
__device__ float g_dc[OD];
__device__ int   g_bsum[128];
__device__ int   g_boff[128];

__global__ void k_zero(){
    int i = blockIdx.x*256 + threadIdx.x;
    if (i < NV)    g_deg[i] = 0;
    if (i < ZD*ZD) g_S[i]   = 0.f;
    if (i < ZD)    g_cs[i]  = 0.f;
}

// ---- folded weights via tiled GEMM: 48 blocks of 32x64 tiles + 1 bias block ----
__global__ void __launch_bounds__(256) k_wfold(const float* __restrict__ fcW,
                          const float* __restrict__ W0, const float* __restrict__ W1,
                          const float* __restrict__ W2,
                          const float* __restrict__ b0, const float* __restrict__ b1,
                          const float* __restrict__ b2, const float* __restrict__ fcb){
    int b = blockIdx.x;
    int tid = threadIdx.x;
    if (b < 48){
        __shared__ float As[32][33];
        __shared__ float Bs[32][64];
        int j   = b / 16;          // hop index 0..2
        int mt  = b % 16;          // ko tile of 32 rows
        int ko0 = mt * 32;
        const float* W = (j==0)?W0:((j==1)?W1:W2);
        int tr = tid >> 4;         // 0..15 -> rows tr*2, tr*2+1
        int tc = tid & 15;         // cols tc*4..tc*4+3
        float acc[2][4] = {};
        for (int kk = 0; kk < HD; kk += 32){
            #pragma unroll
            for (int t = tid; t < 1024; t += 256){
                int r = t >> 5, c = t & 31;
                As[r][c] = fcW[(size_t)(ko0+r)*1536 + j*512 + kk + c];
            }
            #pragma unroll
            for (int t = tid; t < 2048; t += 256){
                int r = t >> 6, c = t & 63;
                Bs[r][c] = W[(kk+r)*64 + c];
            }
            __syncthreads();
            #pragma unroll 8
            for (int k = 0; k < 32; k++){
                float a0 = As[tr*2][k], a1 = As[tr*2+1][k];
                float4 bv = *(const float4*)&Bs[k][tc*4];
                acc[0][0] = fmaf(a0, bv.x, acc[0][0]);
                acc[0][1] = fmaf(a0, bv.y, acc[0][1]);
                acc[0][2] = fmaf(a0, bv.z, acc[0][2]);
                acc[0][3] = fmaf(a0, bv.w, acc[0][3]);
                acc[1][0] = fmaf(a1, bv.x, acc[1][0]);
                acc[1][1] = fmaf(a1, bv.y, acc[1][1]);
                acc[1][2] = fmaf(a1, bv.z, acc[1][2]);
                acc[1][3] = fmaf(a1, bv.w, acc[1][3]);
            }
            __syncthreads();
        }
        #pragma unroll
        for (int r = 0; r < 2; r++){
            int ko = ko0 + tr*2 + r;
            #pragma unroll
            for (int c = 0; c < 4; c++)
                g_M[(size_t)ko*ZD + j*64 + tc*4 + c] = acc[r][c];
        }
    } else {
        // bias fold: c[ko] = fcb[ko] + fcW[ko]·[b0;b1;b2]
        for (int ko = tid; ko < HD; ko += 256){
            const float* fr = fcW + (size_t)ko*1536;
            float s = fcb[ko];
            #pragma unroll 4
            for (int h = 0; h < HD; h++)
                s += fr[h]*b0[h] + fr[512+h]*b1[h] + fr[1024+h]*b2[h];
            g_cv[ko] = s;
        }
    }
}

__global__ void k_deg(const int* __restrict__ dst){
    int e = blockIdx.x*256 + threadIdx.x;
    if (e < NE) atomicAdd(&g_deg[dst[e]], 1);
}

__global__ void k_scan1(){
    __shared__ int sh[1024];
    int t = threadIdx.x, i = blockIdx.x*1024 + t;
    int v = (i < NV) ? g_deg[i] : 0;
    sh[t] = v; __syncthreads();
    for (int off=1; off<1024; off<<=1){
        int x = (t >= off) ? sh[t-off] : 0; __syncthreads();
        sh[t] += x; __syncthreads();
    }
    if (i < NV) g_off[i] = sh[t] - v;
    if (t == 1023) g_bsum[blockIdx.x] = sh[1023];
}

__global__ void k_scan2(){
    __shared__ int sh[128];
    int t = threadIdx.x;
    int v = (t < 98) ? g_bsum[t] : 0;
    sh[t] = v; __syncthreads();
    for (int off=1; off<128; off<<=1){
        int x = (t >= off) ? sh[t-off] : 0; __syncthreads();
        sh[t] += x; __syncthreads();
    }
    g_boff[t] = sh[t] - v;
}

// finalize offsets/cursor/norm AND scale feats -> tA (fused old k_t0)
__global__ void k_scan3t0(const float* __restrict__ feats){
    __shared__ float snorm[256];
    int t = threadIdx.x;
    int i = blockIdx.x*256 + t;
    if (i < NV){
        int o = g_off[i] + g_boff[i >> 10];
        g_off[i] = o; g_cur[i] = o;
        int d = g_deg[i];
        float nv = rsqrtf((float)(d > 1 ? d : 1));
        g_norm[i] = nv;
        snorm[t]  = nv;
    }
    __syncthreads();
    int base = blockIdx.x*256*64;              // float index of first row
    for (int tt = t; tt < 256*16; tt += 256){  // 4096 float4
        int r = tt >> 4;                       // local row
        int gi = base/4 + tt;
        if (blockIdx.x*256 + r < NV){
            float4 v = __ldg(((const float4*)feats) + gi);
            float nv = snorm[r];
            v.x *= nv; v.y *= nv; v.z *= nv; v.w *= nv;
            ((float4*)g_tA)[gi] = v;
        }
    }
}

__global__ void k_place(const int* __restrict__ src, const int* __restrict__ dst){
    int e = blockIdx.x*256 + threadIdx.x;
    if (e < NE){
        int p = atomicAdd(&g_cur[dst[e]], 1);
        g_csc[p] = src[e];
    }
}

// one hop: h[v] = norm[v] * sum_{u in N(v)} t[u]; next t = h*norm (skipped on last)
__global__ void k_hop(int sel, int coff, int wt){
    int gw   = (blockIdx.x*blockDim.x + threadIdx.x) >> 5;
    int lane = threadIdx.x & 31;
    if (gw >= NV) return;
    const float2* tin  = (const float2*)(sel ? g_tB : g_tA);
    float2*       tout = (float2*)(sel ? g_tA : g_tB);
    int s = g_off[gw], e = s + g_deg[gw];
    float ax = 0.f, ay = 0.f;
    int i = s;
    for (; i + 3 < e; i += 4){
        int u0 = g_csc[i], u1 = g_csc[i+1], u2 = g_csc[i+2], u3 = g_csc[i+3];
        float2 a = __ldg(&tin[u0*32 + lane]);
        float2 b = __ldg(&tin[u1*32 + lane]);
        float2 c = __ldg(&tin[u2*32 + lane]);
        float2 d = __ldg(&tin[u3*32 + lane]);
        ax += (a.x + b.x) + (c.x + d.x);
        ay += (a.y + b.y) + (c.y + d.y);
    }
    for (; i < e; i++){
        int u = g_csc[i];
        float2 a = __ldg(&tin[u*32 + lane]);
        ax += a.x; ay += a.y;
    }
    float nv = g_norm[gw];
    float hx = ax*nv, hy = ay*nv;
    ((float2*)(g_H + (size_t)gw*ZD + coff))[lane] = make_float2(hx, hy);
    if (wt) tout[gw*32 + lane] = make_float2(hx*nv, hy*nv);
}

// Gram, upper triangle only: 160 threads, threads 0..135 own one 12x12 tile
__global__ void __launch_bounds__(160) k_gram(){
    __shared__ float zs[64*ZD];        // 48KB
    int tid = threadIdx.x;
    bool active = tid < 136;
    int ti = 0, tj = 0;
    if (active){
        int rem = tid, rowlen = 16;
        while (rem >= rowlen){ rem -= rowlen; rowlen--; ti++; }
        tj = ti + rem;
    }
    bool diag = active && (ti == tj);
    ull acc[12][6];
    #pragma unroll
    for (int a=0;a<12;a++){
        #pragma unroll
        for (int b=0;b<6;b++) acc[a][b] = 0ULL;
    }
    ull csum2[6];
    #pragma unroll
    for (int b=0;b<6;b++) csum2[b] = 0ULL;

    int ntile = (NV + 63) >> 6;
    for (int tile = blockIdx.x; tile < ntile; tile += gridDim.x){
        int r0 = tile << 6;
        int valid = NV - r0; if (valid > 64) valid = 64;
        for (int t = tid; t < 64*ZD/4; t += 160){
            int r = t / (ZD/4);
            float4 v = (r < valid) ? __ldg(((const float4*)(g_H + (size_t)r0*ZD)) + t)
                                   : make_float4(0.f,0.f,0.f,0.f);
            ((float4*)zs)[t] = v;
        }
        __syncthreads();
        if (active){
            for (int r=0; r<64; r++){
                const float* row = zs + r*ZD;
                ull zj[6];
                #pragma unroll
                for (int b=0;b<6;b++) zj[b] = ((const ull*)row)[tj*6 + b];
                if (diag){
                    #pragma unroll
                    for (int b=0;b<6;b++) add2(csum2[b], zj[b]);
                }
                #pragma unroll
                for (int a=0;a<12;a++){
                    float z = row[ti*12 + a];
                    ull zz = pack2(z, z);
                    #pragma unroll
                    for (int b=0;b<6;b++) fma2(acc[a][b], zz, zj[b]);
                }
            }
        }
        __syncthreads();
    }
    if (active){
        #pragma unroll
        for (int a=0;a<12;a++){
            int i = ti*12 + a;
            #pragma unroll
            for (int b=0;b<6;b++){
                float2 p = unpack2(acc[a][b]);
                atomicAdd(&g_S[i*ZD + tj*12 + 2*b],     p.x);
                atomicAdd(&g_S[i*ZD + tj*12 + 2*b + 1], p.y);
            }
        }
        if (diag){
            #pragma unroll
            for (int b=0;b<6;b++){
                float2 p = unpack2(csum2[b]);
                atomicAdd(&g_cs[tj*12 + 2*b],     p.x);
                atomicAdd(&g_cs[tj*12 + 2*b + 1], p.y);
            }
        }
    }
}

__global__ void k_mirror(){
    int idx = blockIdx.x*256 + threadIdx.x;
    if (idx < ZD*ZD){
        int i = idx / ZD, j = idx - i*ZD;
        if (j > i) g_S[j*ZD + i] = g_S[idx];
    }
}

// BN stats per output channel; fold with q
__global__ void k_stats(const float* __restrict__ gamma, const float* __restrict__ beta,
                        const float* __restrict__ q){
    __shared__ float m[ZD], r1[ZD], r2[ZD];
    int ko = blockIdx.x, t = threadIdx.x;
    m[t] = g_M[ko*ZD + t];
    __syncthreads();
    float w = 0.f;
    const float* Srow = g_S + t*ZD;
    #pragma unroll 4
    for (int j=0;j<ZD;j++) w = fmaf(Srow[j], m[j], w);
    r1[t] = m[t]*w;
    r2[t] = m[t]*g_cs[t];
    __syncthreads();
    for (int s=96; s>=3; s>>=1){
        if (t < s){ r1[t] += r1[t+s]; r2[t] += r2[t+s]; }
        __syncthreads();
    }
    if (t == 0){
        float qf  = r1[0]+r1[1]+r1[2];
        float mz  = (r2[0]+r2[1]+r2[2]) * (1.0f/NV);
        float var = qf*(1.0f/NV) - mz*mz;
        float c   = g_cv[ko];
        float inv = rsqrtf(var + EPS);
        float sc  = gamma[ko]*inv;
        float tsh = beta[ko] - (mz + c)*sc;
        float qk  = q[ko >> 6];
        g_av[ko] = qk*sc;
        g_dt[ko] = qk*(sc*c + tsh);
    }
}

__global__ void k_vk(){
    int idx = blockIdx.x*256 + threadIdx.x;
    if (idx < ZD*OD){
        int i = idx >> 6, o = idx & 63;
        float s = 0.f;
        #pragma unroll
        for (int k=0;k<8;k++){ int ko = k*64+o; s = fmaf(g_av[ko], g_M[ko*ZD + i], s); }
        g_V[idx] = s;
    } else if (idx < ZD*OD + OD){
        int o = idx - ZD*OD;
        float s = 0.f;
        #pragma unroll
        for (int k=0;k<8;k++) s += g_dt[k*64+o];
        g_dc[o] = s;
    }
}

// out = H @ V^T + dconst ; 128 rows/block, thread = 4 rows x 8 cols
__global__ void __launch_bounds__(256) k_out(float* __restrict__ out){
    __shared__ float Vs[32*64];
    __shared__ float zs[128*33];
    int tid = threadIdx.x;
    int tc = tid & 7, tr = tid >> 3;
    int r0 = blockIdx.x * 128;
    int valid = NV - r0; if (valid > 128) valid = 128;

    ull acc[4][4];
    #pragma unroll
    for (int a=0;a<4;a++){
        #pragma unroll
        for (int b=0;b<4;b++) acc[a][b] = 0ULL;
    }

    for (int kk=0; kk<ZD; kk+=32){
        for (int t = tid; t < 512; t += 256)
            ((float4*)Vs)[t] = __ldg(((const float4*)(g_V + kk*64)) + t);
        for (int t = tid; t < 1024; t += 256){
            int r = t >> 3, c = t & 7;
            float4 v = (r < valid)
                ? __ldg((const float4*)(g_H + (size_t)(r0+r)*ZD + kk) + c)
                : make_float4(0.f,0.f,0.f,0.f);
            float* d = zs + r*33 + c*4;
            d[0]=v.x; d[1]=v.y; d[2]=v.z; d[3]=v.w;
        }
        __syncthreads();
        #pragma unroll 4
        for (int k=0;k<32;k++){
            ull vv[4];
            #pragma unroll
            for (int c=0;c<4;c++) vv[c] = ((const ull*)(Vs + k*64))[tc*4 + c];
            #pragma unroll
            for (int rr=0;rr<4;rr++){
                float z = zs[(tr*4+rr)*33 + k];
                ull zz = pack2(z, z);
                #pragma unroll
                for (int c=0;c<4;c++) fma2(acc[rr][c], zz, vv[c]);
            }
        }
        __syncthreads();
    }
    #pragma unroll
    for (int rr=0;rr<4;rr++){
        int row = r0 + tr*4 + rr;
        if (row < NV){
            float2* o2 = (float2*)(out + (size_t)row*64 + tc*8);
            #pragma unroll
            for (int c=0;c<4;c++){
                float2 p = unpack2(acc[rr][c]);
                p.x += g_dc[tc*8 + 2*c];
                p.y += g_dc[tc*8 + 2*c + 1];
                o2[c] = p;
            }
        }
    }
}

extern "C" void kernel_launch(void* const* d_in, const int* in_sizes, int n_in,
                              void* d_out, int out_size){
    const float* feats = (const float*)d_in[0];
    const int*   src   = (const int*)  d_in[1];
    const int*   dst   = (const int*)  d_in[2];
    const float* W0    = (const float*)d_in[3];
    const float* b0    = (const float*)d_in[4];
    const float* W1    = (const float*)d_in[5];
    const float* b1    = (const float*)d_in[6];
    const float* W2    = (const float*)d_in[7];
    const float* b2    = (const float*)d_in[8];
    const float* fcW   = (const float*)d_in[9];
    const float* fcb   = (const float*)d_in[10];
    const float* gamma = (const float*)d_in[11];
    const float* beta  = (const float*)d_in[12];
    const float* q     = (const float*)d_in[13];
    float* out = (float*)d_out;

    k_zero   <<<391, 256>>>();
    k_wfold  <<<49, 256>>>(fcW, W0, W1, W2, b0, b1, b2, fcb);
    k_deg    <<<6250, 256>>>(dst);
    k_scan1  <<<98, 1024>>>();
    k_scan2  <<<1, 128>>>();
    k_scan3t0<<<391, 256>>>(feats);
    k_place  <<<6250, 256>>>(src, dst);
    k_hop    <<<12500, 256>>>(0, 0,   1);
    k_hop    <<<12500, 256>>>(1, 64,  1);
    k_hop    <<<12500, 256>>>(0, 128, 0);
    k_gram   <<<296, 160>>>();
    k_mirror <<<144, 256>>>();
    k_stats  <<<512, 192>>>(gamma, beta, q);
    k_vk     <<<49, 256>>>();
    k_out    <<<782, 256>>>(out);
}

// round 4
// speedup vs baseline: 1.2552x; 1.2552x over previous
#include <cuda_runtime.h>

#define NV 100000
#define NE 1600000
#define ZD 192
#define HD 512
#define OD 64
#define EPS 1e-5f

typedef unsigned long long ull;

__device__ __forceinline__ ull pack2(float lo, float hi){
    ull r; asm("mov.b64 %0, {%1,%2};" : "=l"(r) : "f"(lo), "f"(hi)); return r;
}
__device__ __forceinline__ void fma2(ull &d, ull a, ull b){
    asm("fma.rn.f32x2 %0, %1, %2, %0;" : "+l"(d) : "l"(a), "l"(b));
}
__device__ __forceinline__ float2 unpack2(ull v){
    float2 f; asm("mov.b64 {%0,%1}, %2;" : "=f"(f.x), "=f"(f.y) : "l"(v)); return f;
}

// scratch (no allocations allowed)
__device__ int   g_deg[NV];
__device__ int   g_off[NV];
__device__ int   g_cur[NV];
__device__ int   g_csc[NE];
__device__ float g_norm[NV];
__device__ float g_tA[NV*64];
__device__ float g_tB[NV*64];
__device__ float g_H[(size_t)NV*ZD];   // [h1|h2|h3] per node
__device__ float g_S[ZD*ZD];           // Gram
__device__ float g_cs[ZD];             // column sums
__device__ float g_M[HD*ZD];           // folded weights
__device__ float g_cv[HD];             // folded bias
__device__ float g_av[HD];             // q*gamma*invstd
__device__ float g_dt[HD];             // per-channel const
__device__ float g_V[ZD*OD];
__device__ float g_dc[OD];
__device__ int   g_bsum[128];
__device__ int   g_boff[128];

__global__ void k_zero(){
    int i = blockIdx.x*256 + threadIdx.x;
    if (i < NV)    g_deg[i] = 0;
    if (i < ZD*ZD) g_S[i]   = 0.f;
    if (i < ZD)    g_cs[i]  = 0.f;
}

// M_j = fc_W_j @ W_j ; c = fc_W @ [b0;b1;b2] + fc_b   (R2-proven version)
__global__ void k_weights(const float* __restrict__ fcW,
                          const float* __restrict__ W0, const float* __restrict__ W1,
                          const float* __restrict__ W2,
                          const float* __restrict__ b0, const float* __restrict__ b1,
                          const float* __restrict__ b2, const float* __restrict__ fcb){
    int idx = blockIdx.x*256 + threadIdx.x;
    if (idx < HD*ZD){
        int ko = idx / ZD, i = idx - ko*ZD;
        int j = i >> 6, d = i & 63;
        const float* W  = (j==0)?W0:((j==1)?W1:W2);
        const float* fr = fcW + ko*1536 + j*512;
        float s = 0.f;
        #pragma unroll 4
        for (int h=0; h<HD; h++) s = fmaf(fr[h], W[h*64+d], s);
        g_M[ko*ZD+i] = s;
    } else if (idx < HD*ZD + HD){
        int ko = idx - HD*ZD;
        const float* fr = fcW + ko*1536;
        float s = fcb[ko];
        for (int h=0; h<HD; h++)
            s += fr[h]*b0[h] + fr[512+h]*b1[h] + fr[1024+h]*b2[h];
        g_cv[ko] = s;
    }
}

__global__ void k_deg(const int* __restrict__ dst){
    int e = blockIdx.x*256 + threadIdx.x;
    if (e < NE) atomicAdd(&g_deg[dst[e]], 1);
}

__global__ void k_scan1(){
    __shared__ int sh[1024];
    int t = threadIdx.x, i = blockIdx.x*1024 + t;
    int v = (i < NV) ? g_deg[i] : 0;
    sh[t] = v; __syncthreads();
    for (int off=1; off<1024; off<<=1){
        int x = (t >= off) ? sh[t-off] : 0; __syncthreads();
        sh[t] += x; __syncthreads();
    }
    if (i < NV) g_off[i] = sh[t] - v;
    if (t == 1023) g_bsum[blockIdx.x] = sh[1023];
}

__global__ void k_scan2(){
    __shared__ int sh[128];
    int t = threadIdx.x;
    int v = (t < 98) ? g_bsum[t] : 0;
    sh[t] = v; __syncthreads();
    for (int off=1; off<128; off<<=1){
        int x = (t >= off) ? sh[t-off] : 0; __syncthreads();
        sh[t] += x; __syncthreads();
    }
    g_boff[t] = sh[t] - v;
}

// finalize offsets/cursor/norm AND scale feats -> tA
__global__ void k_scan3t0(const float* __restrict__ feats){
    __shared__ float snorm[256];
    int t = threadIdx.x;
    int i = blockIdx.x*256 + t;
    if (i < NV){
        int o = g_off[i] + g_boff[i >> 10];
        g_off[i] = o; g_cur[i] = o;
        int d = g_deg[i];
        float nv = rsqrtf((float)(d > 1 ? d : 1));
        g_norm[i] = nv;
        snorm[t]  = nv;
    }
    __syncthreads();
    int base4 = blockIdx.x*256*16;             // float4 index of first row
    for (int tt = t; tt < 256*16; tt += 256){
        int r = tt >> 4;
        if (blockIdx.x*256 + r < NV){
            float4 v = __ldg(((const float4*)feats) + base4 + tt);
            float nv = snorm[r];
            v.x *= nv; v.y *= nv; v.z *= nv; v.w *= nv;
            ((float4*)g_tA)[base4 + tt] = v;
        }
    }
}

__global__ void k_place(const int* __restrict__ src, const int* __restrict__ dst){
    int e = blockIdx.x*256 + threadIdx.x;
    if (e < NE){
        int p = atomicAdd(&g_cur[dst[e]], 1);
        g_csc[p] = src[e];
    }
}

// hop: warp per node; half-warp per neighbor, float4 per lane (16B x 16 lanes = 256B row)
__global__ void k_hop(int sel, int coff, int wt){
    int gw   = (blockIdx.x*blockDim.x + threadIdx.x) >> 5;
    int lane = threadIdx.x & 31;
    if (gw >= NV) return;
    const float4* tin  = (const float4*)(sel ? g_tB : g_tA);
    float4*       tout = (float4*)(sel ? g_tA : g_tB);
    int s = g_off[gw], e = s + g_deg[gw];
    int half = lane >> 4;     // which neighbor of the pair
    int c4   = lane & 15;     // which 16B chunk of the 64-float row
    float ax=0.f, ay=0.f, az=0.f, aw=0.f;
    int i = s;
    for (; i + 3 < e; i += 4){
        int ua = g_csc[i + half];
        int ub = g_csc[i + 2 + half];
        float4 va = __ldg(&tin[ua*16 + c4]);
        float4 vb = __ldg(&tin[ub*16 + c4]);
        ax += va.x + vb.x; ay += va.y + vb.y;
        az += va.z + vb.z; aw += va.w + vb.w;
    }
    if (i + 1 < e){
        int u = g_csc[i + half];
        float4 v = __ldg(&tin[u*16 + c4]);
        ax += v.x; ay += v.y; az += v.z; aw += v.w;
        i += 2;
    }
    if (i < e && half == 0){
        int u = g_csc[i];
        float4 v = __ldg(&tin[u*16 + c4]);
        ax += v.x; ay += v.y; az += v.z; aw += v.w;
    }
    ax += __shfl_xor_sync(0xffffffffu, ax, 16);
    ay += __shfl_xor_sync(0xffffffffu, ay, 16);
    az += __shfl_xor_sync(0xffffffffu, az, 16);
    aw += __shfl_xor_sync(0xffffffffu, aw, 16);
    if (half == 0){
        float nv = g_norm[gw];
        float4 h = make_float4(ax*nv, ay*nv, az*nv, aw*nv);
        ((float4*)(g_H + (size_t)gw*ZD + coff))[c4] = h;
        if (wt){
            float4 tv = make_float4(h.x*nv, h.y*nv, h.z*nv, h.w*nv);
            tout[gw*16 + c4] = tv;
        }
    }
}

// Gram: R2-proven full version. 148 persistent blocks, 16x16 threads, 12x12 reg tiles
__global__ void __launch_bounds__(256,1) k_gram(){
    __shared__ float zs[64*ZD];        // 48KB
    int tid = threadIdx.x, ti = tid & 15, tj = tid >> 4;
    ull acc[12][6];
    #pragma unroll
    for (int a=0;a<12;a++){
        #pragma unroll
        for (int b=0;b<6;b++) acc[a][b] = 0ULL;
    }
    float csum[12];
    #pragma unroll
    for (int a=0;a<12;a++) csum[a] = 0.f;

    int ntile = (NV + 63) >> 6;
    for (int tile = blockIdx.x; tile < ntile; tile += gridDim.x){
        int r0 = tile << 6;
        int valid = NV - r0; if (valid > 64) valid = 64;
        for (int t = tid; t < 64*ZD/4; t += 256){
            int r = t / (ZD/4);
            float4 v = (r < valid) ? __ldg(((const float4*)(g_H + (size_t)r0*ZD)) + t)
                                   : make_float4(0.f,0.f,0.f,0.f);
            ((float4*)zs)[t] = v;
        }
        __syncthreads();
        for (int r=0; r<64; r++){
            const float* row = zs + r*ZD;
            ull zj[6];
            #pragma unroll
            for (int b=0;b<6;b++) zj[b] = ((const ull*)row)[tj*6 + b];
            #pragma unroll
            for (int a=0;a<12;a++){
                float z = row[ti*12 + a];
                if (tj == 0) csum[a] += z;
                ull zz = pack2(z, z);
                #pragma unroll
                for (int b=0;b<6;b++) fma2(acc[a][b], zz, zj[b]);
            }
        }
        __syncthreads();
    }
    #pragma unroll
    for (int a=0;a<12;a++){
        int i = ti*12 + a;
        #pragma unroll
        for (int b=0;b<6;b++){
            float2 p = unpack2(acc[a][b]);
            atomicAdd(&g_S[i*ZD + tj*12 + 2*b],     p.x);
            atomicAdd(&g_S[i*ZD + tj*12 + 2*b + 1], p.y);
        }
    }
    if (tj == 0){
        #pragma unroll
        for (int a=0;a<12;a++) atomicAdd(&g_cs[ti*12 + a], csum[a]);
    }
}

// BN stats per output channel; fold with q
__global__ void k_stats(const float* __restrict__ gamma, const float* __restrict__ beta,
                        const float* __restrict__ q){
    __shared__ float m[ZD], r1[ZD], r2[ZD];
    int ko = blockIdx.x, t = threadIdx.x;
    m[t] = g_M[ko*ZD + t];
    __syncthreads();
    float w = 0.f;
    const float* Srow = g_S + t*ZD;
    #pragma unroll 4
    for (int j=0;j<ZD;j++) w = fmaf(Srow[j], m[j], w);
    r1[t] = m[t]*w;
    r2[t] = m[t]*g_cs[t];
    __syncthreads();
    for (int s=96; s>=3; s>>=1){
        if (t < s){ r1[t] += r1[t+s]; r2[t] += r2[t+s]; }
        __syncthreads();
    }
    if (t == 0){
        float qf  = r1[0]+r1[1]+r1[2];
        float mz  = (r2[0]+r2[1]+r2[2]) * (1.0f/NV);
        float var = qf*(1.0f/NV) - mz*mz;
        float c   = g_cv[ko];
        float inv = rsqrtf(var + EPS);
        float sc  = gamma[ko]*inv;
        float tsh = beta[ko] - (mz + c)*sc;
        float qk  = q[ko >> 6];
        g_av[ko] = qk*sc;
        g_dt[ko] = qk*(sc*c + tsh);
    }
}

__global__ void k_vk(){
    int idx = blockIdx.x*256 + threadIdx.x;
    if (idx < ZD*OD){
        int i = idx >> 6, o = idx & 63;
        float s = 0.f;
        #pragma unroll
        for (int k=0;k<8;k++){ int ko = k*64+o; s = fmaf(g_av[ko], g_M[ko*ZD + i], s); }
        g_V[idx] = s;
    } else if (idx < ZD*OD + OD){
        int o = idx - ZD*OD;
        float s = 0.f;
        #pragma unroll
        for (int k=0;k<8;k++) s += g_dt[k*64+o];
        g_dc[o] = s;
    }
}

// out = H @ V^T + dconst ; 128 rows/block, thread = 4 rows x 8 cols
__global__ void __launch_bounds__(256) k_out(float* __restrict__ out){
    __shared__ float Vs[32*64];
    __shared__ float zs[128*33];
    int tid = threadIdx.x;
    int tc = tid & 7, tr = tid >> 3;
    int r0 = blockIdx.x * 128;
    int valid = NV - r0; if (valid > 128) valid = 128;

    ull acc[4][4];
    #pragma unroll
    for (int a=0;a<4;a++){
        #pragma unroll
        for (int b=0;b<4;b++) acc[a][b] = 0ULL;
    }

    for (int kk=0; kk<ZD; kk+=32){
        for (int t = tid; t < 512; t += 256)
            ((float4*)Vs)[t] = __ldg(((const float4*)(g_V + kk*64)) + t);
        for (int t = tid; t < 1024; t += 256){
            int r = t >> 3, c = t & 7;
            float4 v = (r < valid)
                ? __ldg((const float4*)(g_H + (size_t)(r0+r)*ZD + kk) + c)
                : make_float4(0.f,0.f,0.f,0.f);
            float* d = zs + r*33 + c*4;
            d[0]=v.x; d[1]=v.y; d[2]=v.z; d[3]=v.w;
        }
        __syncthreads();
        #pragma unroll 4
        for (int k=0;k<32;k++){
            ull vv[4];
            #pragma unroll
            for (int c=0;c<4;c++) vv[c] = ((const ull*)(Vs + k*64))[tc*4 + c];
            #pragma unroll
            for (int rr=0;rr<4;rr++){
                float z = zs[(tr*4+rr)*33 + k];
                ull zz = pack2(z, z);
                #pragma unroll
                for (int c=0;c<4;c++) fma2(acc[rr][c], zz, vv[c]);
            }
        }
        __syncthreads();
    }
    #pragma unroll
    for (int rr=0;rr<4;rr++){
        int row = r0 + tr*4 + rr;
        if (row < NV){
            float2* o2 = (float2*)(out + (size_t)row*64 + tc*8);
            #pragma unroll
            for (int c=0;c<4;c++){
                float2 p = unpack2(acc[rr][c]);
                p.x += g_dc[tc*8 + 2*c];
                p.y += g_dc[tc*8 + 2*c + 1];
                o2[c] = p;
            }
        }
    }
}

extern "C" void kernel_launch(void* const* d_in, const int* in_sizes, int n_in,
                              void* d_out, int out_size){
    const float* feats = (const float*)d_in[0];
    const int*   src   = (const int*)  d_in[1];
    const int*   dst   = (const int*)  d_in[2];
    const float* W0    = (const float*)d_in[3];
    const float* b0    = (const float*)d_in[4];
    const float* W1    = (const float*)d_in[5];
    const float* b1    = (const float*)d_in[6];
    const float* W2    = (const float*)d_in[7];
    const float* b2    = (const float*)d_in[8];
    const float* fcW   = (const float*)d_in[9];
    const float* fcb   = (const float*)d_in[10];
    const float* gamma = (const float*)d_in[11];
    const float* beta  = (const float*)d_in[12];
    const float* q     = (const float*)d_in[13];
    float* out = (float*)d_out;

    k_zero   <<<391, 256>>>();
    k_weights<<<387, 256>>>(fcW, W0, W1, W2, b0, b1, b2, fcb);
    k_deg    <<<6250, 256>>>(dst);
    k_scan1  <<<98, 1024>>>();
    k_scan2  <<<1, 128>>>();
    k_scan3t0<<<391, 256>>>(feats);
    k_place  <<<6250, 256>>>(src, dst);
    k_hop    <<<12500, 256>>>(0, 0,   1);
    k_hop    <<<12500, 256>>>(1, 64,  1);
    k_hop    <<<12500, 256>>>(0, 128, 0);
    k_gram   <<<148, 256>>>();
    k_stats  <<<512, 192>>>(gamma, beta, q);
    k_vk     <<<49, 256>>>();
    k_out    <<<782, 256>>>(out);
}

// round 7
// speedup vs baseline: 1.3636x; 1.0864x over previous
#include <cuda_runtime.h>

#define NV 100000
#define NE 1600000
#define ZD 192
#define HD 512
#define OD 64
#define EPS 1e-5f

typedef unsigned long long ull;

__device__ __forceinline__ ull pack2(float lo, float hi){
    ull r; asm("mov.b64 %0, {%1,%2};" : "=l"(r) : "f"(lo), "f"(hi)); return r;
}
__device__ __forceinline__ void fma2(ull &d, ull a, ull b){
    asm("fma.rn.f32x2 %0, %1, %2, %0;" : "+l"(d) : "l"(a), "l"(b));
}
__device__ __forceinline__ float2 unpack2(ull v){
    float2 f; asm("mov.b64 {%0,%1}, %2;" : "=f"(f.x), "=f"(f.y) : "l"(v)); return f;
}

// symmetric gram tile list: S tiled (32 rows x 16 cols); keep J >= 2I  (42 tiles)
__constant__ unsigned char c_tI[42] = {0,0,0,0,0,0,0,0,0,0,0,0,
                                       1,1,1,1,1,1,1,1,1,1,
                                       2,2,2,2,2,2,2,2,
                                       3,3,3,3,3,3,
                                       4,4,4,4,
                                       5,5};
__constant__ unsigned char c_tJ[42] = {0,1,2,3,4,5,6,7,8,9,10,11,
                                       2,3,4,5,6,7,8,9,10,11,
                                       4,5,6,7,8,9,10,11,
                                       6,7,8,9,10,11,
                                       8,9,10,11,
                                       10,11};

// scratch (no allocations allowed)
__device__ int   g_deg[NV];
__device__ int   g_off[NV];
__device__ int   g_cur[NV];
__device__ int   g_csc[NE];
__device__ float g_norm[NV];
__device__ float g_tA[NV*64];
__device__ float g_tB[NV*64];
__device__ float g_H[(size_t)NV*ZD];   // [h1|h2|h3] per node
__device__ float g_S[ZD*ZD];           // Gram (upper triangle authoritative)
__device__ float g_cs[ZD];             // column sums
__device__ float g_M[HD*ZD];           // folded weights
__device__ float g_cv[HD];             // folded bias
__device__ float g_av[HD];             // q*gamma*invstd
__device__ float g_dt[HD];             // per-channel const
__device__ float g_V[ZD*OD];
__device__ float g_dc[OD];
__device__ int   g_bsum[128];
__device__ int   g_boff[128];

__global__ void k_zero(){
    int i = blockIdx.x*256 + threadIdx.x;
    if (i < NV)    g_deg[i] = 0;
    if (i < ZD*ZD) g_S[i]   = 0.f;
    if (i < ZD)    g_cs[i]  = 0.f;
}

// M_j = fc_W_j @ W_j ; c = fc_W @ [b0;b1;b2] + fc_b
__global__ void k_weights(const float* __restrict__ fcW,
                          const float* __restrict__ W0, const float* __restrict__ W1,
                          const float* __restrict__ W2,
                          const float* __restrict__ b0, const float* __restrict__ b1,
                          const float* __restrict__ b2, const float* __restrict__ fcb){
    int idx = blockIdx.x*256 + threadIdx.x;
    if (idx < HD*ZD){
        int ko = idx / ZD, i = idx - ko*ZD;
        int j = i >> 6, d = i & 63;
        const float* W  = (j==0)?W0:((j==1)?W1:W2);
        const float* fr = fcW + ko*1536 + j*512;
        float s = 0.f;
        #pragma unroll 4
        for (int h=0; h<HD; h++) s = fmaf(fr[h], W[h*64+d], s);
        g_M[ko*ZD+i] = s;
    } else if (idx < HD*ZD + HD){
        int ko = idx - HD*ZD;
        const float* fr = fcW + ko*1536;
        float s = fcb[ko];
        for (int h=0; h<HD; h++)
            s += fr[h]*b0[h] + fr[512+h]*b1[h] + fr[1024+h]*b2[h];
        g_cv[ko] = s;
    }
}

__global__ void k_deg(const int* __restrict__ dst){
    int e = blockIdx.x*256 + threadIdx.x;
    if (e < NE) atomicAdd(&g_deg[dst[e]], 1);
}

__global__ void k_scan1(){
    __shared__ int sh[1024];
    int t = threadIdx.x, i = blockIdx.x*1024 + t;
    int v = (i < NV) ? g_deg[i] : 0;
    sh[t] = v; __syncthreads();
    for (int off=1; off<1024; off<<=1){
        int x = (t >= off) ? sh[t-off] : 0; __syncthreads();
        sh[t] += x; __syncthreads();
    }
    if (i < NV) g_off[i] = sh[t] - v;
    if (t == 1023) g_bsum[blockIdx.x] = sh[1023];
}

__global__ void k_scan2(){
    __shared__ int sh[128];
    int t = threadIdx.x;
    int v = (t < 98) ? g_bsum[t] : 0;
    sh[t] = v; __syncthreads();
    for (int off=1; off<128; off<<=1){
        int x = (t >= off) ? sh[t-off] : 0; __syncthreads();
        sh[t] += x; __syncthreads();
    }
    g_boff[t] = sh[t] - v;
}

// finalize offsets/cursor/norm AND scale feats -> tA
__global__ void k_scan3t0(const float* __restrict__ feats){
    __shared__ float snorm[256];
    int t = threadIdx.x;
    int i = blockIdx.x*256 + t;
    if (i < NV){
        int o = g_off[i] + g_boff[i >> 10];
        g_off[i] = o; g_cur[i] = o;
        int d = g_deg[i];
        float nv = rsqrtf((float)(d > 1 ? d : 1));
        g_norm[i] = nv;
        snorm[t]  = nv;
    }
    __syncthreads();
    int base4 = blockIdx.x*256*16;
    for (int tt = t; tt < 256*16; tt += 256){
        int r = tt >> 4;
        if (blockIdx.x*256 + r < NV){
            float4 v = __ldg(((const float4*)feats) + base4 + tt);
            float nv = snorm[r];
            v.x *= nv; v.y *= nv; v.z *= nv; v.w *= nv;
            ((float4*)g_tA)[base4 + tt] = v;
        }
    }
}

__global__ void k_place(const int* __restrict__ src, const int* __restrict__ dst){
    int e = blockIdx.x*256 + threadIdx.x;
    if (e < NE){
        int p = atomicAdd(&g_cur[dst[e]], 1);
        g_csc[p] = src[e];
    }
}

// hop: warp per node; half-warp per neighbor, float4 per lane; 8-edge unroll
__global__ void k_hop(int sel, int coff, int wt){
    int gw   = (blockIdx.x*blockDim.x + threadIdx.x) >> 5;
    int lane = threadIdx.x & 31;
    if (gw >= NV) return;
    const float4* tin  = (const float4*)(sel ? g_tB : g_tA);
    float4*       tout = (float4*)(sel ? g_tA : g_tB);
    int s = g_off[gw], e = s + g_deg[gw];
    int half = lane >> 4;
    int c4   = lane & 15;
    float ax=0.f, ay=0.f, az=0.f, aw=0.f;
    int i = s;
    for (; i + 7 < e; i += 8){
        int u0 = g_csc[i + half];
        int u1 = g_csc[i + 2 + half];
        int u2 = g_csc[i + 4 + half];
        int u3 = g_csc[i + 6 + half];
        float4 v0 = __ldg(&tin[u0*16 + c4]);
        float4 v1 = __ldg(&tin[u1*16 + c4]);
        float4 v2 = __ldg(&tin[u2*16 + c4]);
        float4 v3 = __ldg(&tin[u3*16 + c4]);
        ax += (v0.x + v1.x) + (v2.x + v3.x);
        ay += (v0.y + v1.y) + (v2.y + v3.y);
        az += (v0.z + v1.z) + (v2.z + v3.z);
        aw += (v0.w + v1.w) + (v2.w + v3.w);
    }
    for (; i + 1 < e; i += 2){
        int u = g_csc[i + half];
        float4 v = __ldg(&tin[u*16 + c4]);
        ax += v.x; ay += v.y; az += v.z; aw += v.w;
    }
    if (i < e && half == 0){
        int u = g_csc[i];
        float4 v = __ldg(&tin[u*16 + c4]);
        ax += v.x; ay += v.y; az += v.z; aw += v.w;
    }
    ax += __shfl_xor_sync(0xffffffffu, ax, 16);
    ay += __shfl_xor_sync(0xffffffffu, ay, 16);
    az += __shfl_xor_sync(0xffffffffu, az, 16);
    aw += __shfl_xor_sync(0xffffffffu, aw, 16);
    if (half == 0){
        float nv = g_norm[gw];
        float4 h = make_float4(ax*nv, ay*nv, az*nv, aw*nv);
        ((float4*)(g_H + (size_t)gw*ZD + coff))[c4] = h;
        if (wt){
            float4 tv = make_float4(h.x*nv, h.y*nv, h.z*nv, h.w*nv);
            tout[gw*16 + c4] = tv;
        }
    }
}

// symmetric Gram: 512 threads, warp-uniform 32x16 tiles of upper triangle
__global__ void __launch_bounds__(512,1) k_gram(){
    __shared__ __align__(16) float zs[64*ZD];   // 48KB
    int tid = threadIdx.x;
    int w = tid >> 5, lane = tid & 31;
    int nt = (w < 10) ? 3 : 2;                  // 42 = 10*3 + 6*2
    int rowb[3], colb[3];
    #pragma unroll
    for (int k=0;k<3;k++){
        int t = w + 16*k;
        if (t < 42){ rowb[k] = c_tI[t]*32 + lane; colb[k] = c_tJ[t]*16; }
        else       { rowb[k] = 0;                colb[k] = 0; }
    }
    ull acc[3][8];
    #pragma unroll
    for (int k=0;k<3;k++){
        #pragma unroll
        for (int m=0;m<8;m++) acc[k][m] = 0ULL;
    }
    float csacc = 0.f;

    int ntile = (NV + 63) >> 6;
    for (int tile = blockIdx.x; tile < ntile; tile += gridDim.x){
        int r0 = tile << 6;
        int valid = NV - r0; if (valid > 64) valid = 64;
        for (int t = tid; t < 64*ZD/4; t += 512){
            int r = t / (ZD/4);
            float4 v = (r < valid) ? __ldg(((const float4*)(g_H + (size_t)r0*ZD)) + t)
                                   : make_float4(0.f,0.f,0.f,0.f);
            ((float4*)zs)[t] = v;
        }
        __syncthreads();
        #pragma unroll
        for (int k=0;k<3;k++){
            if (k >= nt) break;
            int rb = rowb[k], cb = colb[k];
            #pragma unroll 4
            for (int r=0; r<64; r++){
                const float* row = zs + r*ZD;
                float zi = row[rb];
                ull zz = pack2(zi, zi);
                ulonglong2 p0 = *(const ulonglong2*)(row + cb);
                ulonglong2 p1 = *(const ulonglong2*)(row + cb + 4);
                ulonglong2 p2 = *(const ulonglong2*)(row + cb + 8);
                ulonglong2 p3 = *(const ulonglong2*)(row + cb + 12);
                fma2(acc[k][0], zz, p0.x); fma2(acc[k][1], zz, p0.y);
                fma2(acc[k][2], zz, p1.x); fma2(acc[k][3], zz, p1.y);
                fma2(acc[k][4], zz, p2.x); fma2(acc[k][5], zz, p2.y);
                fma2(acc[k][6], zz, p3.x); fma2(acc[k][7], zz, p3.y);
            }
        }
        // column sums (threads 0..191, conflict-free: stride 192 words = bank-aligned)
        if (tid < ZD){
            float s = 0.f;
            #pragma unroll 8
            for (int r=0; r<64; r++) s += zs[r*ZD + tid];
            csacc += s;
        }
        __syncthreads();
    }
    #pragma unroll
    for (int k=0;k<3;k++){
        if (k >= nt) break;
        int rb = rowb[k], cb = colb[k];
        #pragma unroll
        for (int m=0;m<8;m++){
            float2 p = unpack2(acc[k][m]);
            atomicAdd(&g_S[rb*ZD + cb + 2*m],     p.x);
            atomicAdd(&g_S[rb*ZD + cb + 2*m + 1], p.y);
        }
    }
    if (tid < ZD) atomicAdd(&g_cs[tid], csacc);
}

// BN stats per output channel (reads upper triangle of S); fold with q
__global__ void k_stats(const float* __restrict__ gamma, const float* __restrict__ beta,
                        const float* __restrict__ q){
    __shared__ float m[ZD], r1[ZD], r2[ZD];
    int ko = blockIdx.x, t = threadIdx.x;
    m[t] = g_M[ko*ZD + t];
    __syncthreads();
    float w = 0.f;
    #pragma unroll 4
    for (int j=0;j<ZD;j++){
        float sv = (j >= t) ? g_S[t*ZD + j] : g_S[j*ZD + t];
        w = fmaf(sv, m[j], w);
    }
    r1[t] = m[t]*w;
    r2[t] = m[t]*g_cs[t];
    __syncthreads();
    for (int s=96; s>=3; s>>=1){
        if (t < s){ r1[t] += r1[t+s]; r2[t] += r2[t+s]; }
        __syncthreads();
    }
    if (t == 0){
        float qf  = r1[0]+r1[1]+r1[2];
        float mz  = (r2[0]+r2[1]+r2[2]) * (1.0f/NV);
        float var = qf*(1.0f/NV) - mz*mz;
        float c   = g_cv[ko];
        float inv = rsqrtf(var + EPS);
        float sc  = gamma[ko]*inv;
        float tsh = beta[ko] - (mz + c)*sc;
        float qk  = q[ko >> 6];
        g_av[ko] = qk*sc;
        g_dt[ko] = qk*(sc*c + tsh);
    }
}

__global__ void k_vk(){
    int idx = blockIdx.x*256 + threadIdx.x;
    if (idx < ZD*OD){
        int i = idx >> 6, o = idx & 63;
        float s = 0.f;
        #pragma unroll
        for (int k=0;k<8;k++){ int ko = k*64+o; s = fmaf(g_av[ko], g_M[ko*ZD + i], s); }
        g_V[idx] = s;
    } else if (idx < ZD*OD + OD){
        int o = idx - ZD*OD;
        float s = 0.f;
        #pragma unroll
        for (int k=0;k<8;k++) s += g_dt[k*64+o];
        g_dc[o] = s;
    }
}

// out = H @ V^T + dconst ; 128 rows/block, thread = 4 rows x 8 cols
__global__ void __launch_bounds__(256) k_out(float* __restrict__ out){
    __shared__ float Vs[32*64];
    __shared__ float zs[128*33];
    int tid = threadIdx.x;
    int tc = tid & 7, tr = tid >> 3;
    int r0 = blockIdx.x * 128;
    int valid = NV - r0; if (valid > 128) valid = 128;

    ull acc[4][4];
    #pragma unroll
    for (int a=0;a<4;a++){
        #pragma unroll
        for (int b=0;b<4;b++) acc[a][b] = 0ULL;
    }

    for (int kk=0; kk<ZD; kk+=32){
        for (int t = tid; t < 512; t += 256)
            ((float4*)Vs)[t] = __ldg(((const float4*)(g_V + kk*64)) + t);
        for (int t = tid; t < 1024; t += 256){
            int r = t >> 3, c = t & 7;
            float4 v = (r < valid)
                ? __ldg((const float4*)(g_H + (size_t)(r0+r)*ZD + kk) + c)
                : make_float4(0.f,0.f,0.f,0.f);
            float* d = zs + r*33 + c*4;
            d[0]=v.x; d[1]=v.y; d[2]=v.z; d[3]=v.w;
        }
        __syncthreads();
        #pragma unroll 4
        for (int k=0;k<32;k++){
            ull vv[4];
            #pragma unroll
            for (int c=0;c<4;c++) vv[c] = ((const ull*)(Vs + k*64))[tc*4 + c];
            #pragma unroll
            for (int rr=0;rr<4;rr++){
                float z = zs[(tr*4+rr)*33 + k];
                ull zz = pack2(z, z);
                #pragma unroll
                for (int c=0;c<4;c++) fma2(acc[rr][c], zz, vv[c]);
            }
        }
        __syncthreads();
    }
    #pragma unroll
    for (int rr=0;rr<4;rr++){
        int row = r0 + tr*4 + rr;
        if (row < NV){
            float2* o2 = (float2*)(out + (size_t)row*64 + tc*8);
            #pragma unroll
            for (int c=0;c<4;c++){
                float2 p = unpack2(acc[rr][c]);
                p.x += g_dc[tc*8 + 2*c];
                p.y += g_dc[tc*8 + 2*c + 1];
                o2[c] = p;
            }
        }
    }
}

extern "C" void kernel_launch(void* const* d_in, const int* in_sizes, int n_in,
                              void* d_out, int out_size){
    const float* feats = (const float*)d_in[0];
    const int*   src   = (const int*)  d_in[1];
    const int*   dst   = (const int*)  d_in[2];
    const float* W0    = (const float*)d_in[3];
    const float* b0    = (const float*)d_in[4];
    const float* W1    = (const float*)d_in[5];
    const float* b1    = (const float*)d_in[6];
    const float* W2    = (const float*)d_in[7];
    const float* b2    = (const float*)d_in[8];
    const float* fcW   = (const float*)d_in[9];
    const float* fcb   = (const float*)d_in[10];
    const float* gamma = (const float*)d_in[11];
    const float* beta  = (const float*)d_in[12];
    const float* q     = (const float*)d_in[13];
    float* out = (float*)d_out;

    k_zero   <<<391, 256>>>();
    k_weights<<<387, 256>>>(fcW, W0, W1, W2, b0, b1, b2, fcb);
    k_deg    <<<6250, 256>>>(dst);
    k_scan1  <<<98, 1024>>>();
    k_scan2  <<<1, 128>>>();
    k_scan3t0<<<391, 256>>>(feats);
    k_place  <<<6250, 256>>>(src, dst);
    k_hop    <<<12500, 256>>>(0, 0,   1);
    k_hop    <<<12500, 256>>>(1, 64,  1);
    k_hop    <<<12500, 256>>>(0, 128, 0);
    k_gram   <<<148, 512>>>();
    k_stats  <<<512, 192>>>(gamma, beta, q);
    k_vk     <<<49, 256>>>();
    k_out    <<<782, 256>>>(out);
}

// round 8
// speedup vs baseline: 1.3908x; 1.0199x over previous
#include <cuda_runtime.h>
#include <cuda_fp16.h>

#define NV 100000
#define NE 1600000
#define ZD 192
#define HD 512
#define OD 64
#define EPS 1e-5f

typedef unsigned long long ull;

__device__ __forceinline__ ull pack2(float lo, float hi){
    ull r; asm("mov.b64 %0, {%1,%2};" : "=l"(r) : "f"(lo), "f"(hi)); return r;
}
__device__ __forceinline__ void fma2(ull &d, ull a, ull b){
    asm("fma.rn.f32x2 %0, %1, %2, %0;" : "+l"(d) : "l"(a), "l"(b));
}
__device__ __forceinline__ float2 unpack2(ull v){
    float2 f; asm("mov.b64 {%0,%1}, %2;" : "=f"(f.x), "=f"(f.y) : "l"(v)); return f;
}

// symmetric gram tile list: S tiled (32 rows x 16 cols); keep J >= 2I  (42 tiles)
__constant__ unsigned char c_tI[42] = {0,0,0,0,0,0,0,0,0,0,0,0,
                                       1,1,1,1,1,1,1,1,1,1,
                                       2,2,2,2,2,2,2,2,
                                       3,3,3,3,3,3,
                                       4,4,4,4,
                                       5,5};
__constant__ unsigned char c_tJ[42] = {0,1,2,3,4,5,6,7,8,9,10,11,
                                       2,3,4,5,6,7,8,9,10,11,
                                       4,5,6,7,8,9,10,11,
                                       6,7,8,9,10,11,
                                       8,9,10,11,
                                       10,11};

// scratch (no allocations allowed)
__device__ int   g_deg[NV];
__device__ int   g_off[NV];
__device__ int   g_cur[NV];
__device__ int   g_csc[NE];
__device__ float g_norm[NV];
__device__ uint2 g_tA16[NV*16];        // fp16 t, 64 halves/row = 128B
__device__ uint2 g_tB16[NV*16];
__device__ float g_H[(size_t)NV*ZD];   // [h1|h2|h3] per node (fp32)
__device__ float g_S[ZD*ZD];           // Gram (upper triangle authoritative)
__device__ float g_cs[ZD];             // column sums
__device__ float g_M[HD*ZD];           // folded weights
__device__ float g_cv[HD];             // folded bias
__device__ float g_av[HD];             // q*gamma*invstd
__device__ float g_dt[HD];             // per-channel const
__device__ float g_V[ZD*OD];
__device__ float g_dc[OD];
__device__ int   g_bsum[128];

__global__ void k_zero(){
    int i = blockIdx.x*256 + threadIdx.x;
    if (i < NV)    g_deg[i] = 0;
    if (i < ZD*ZD) g_S[i]   = 0.f;
    if (i < ZD)    g_cs[i]  = 0.f;
}

// M_j = fc_W_j @ W_j ; c = fc_W @ [b0;b1;b2] + fc_b
__global__ void k_weights(const float* __restrict__ fcW,
                          const float* __restrict__ W0, const float* __restrict__ W1,
                          const float* __restrict__ W2,
                          const float* __restrict__ b0, const float* __restrict__ b1,
                          const float* __restrict__ b2, const float* __restrict__ fcb){
    int idx = blockIdx.x*256 + threadIdx.x;
    if (idx < HD*ZD){
        int ko = idx / ZD, i = idx - ko*ZD;
        int j = i >> 6, d = i & 63;
        const float* W  = (j==0)?W0:((j==1)?W1:W2);
        const float* fr = fcW + ko*1536 + j*512;
        float s = 0.f;
        #pragma unroll 4
        for (int h=0; h<HD; h++) s = fmaf(fr[h], W[h*64+d], s);
        g_M[ko*ZD+i] = s;
    } else if (idx < HD*ZD + HD){
        int ko = idx - HD*ZD;
        const float* fr = fcW + ko*1536;
        float s = fcb[ko];
        for (int h=0; h<HD; h++)
            s += fr[h]*b0[h] + fr[512+h]*b1[h] + fr[1024+h]*b2[h];
        g_cv[ko] = s;
    }
}

__global__ void k_deg(const int* __restrict__ dst){
    int e = blockIdx.x*256 + threadIdx.x;
    if (e < NE) atomicAdd(&g_deg[dst[e]], 1);
}

__global__ void k_scan1(){
    __shared__ int sh[1024];
    int t = threadIdx.x, i = blockIdx.x*1024 + t;
    int v = (i < NV) ? g_deg[i] : 0;
    sh[t] = v; __syncthreads();
    for (int off=1; off<1024; off<<=1){
        int x = (t >= off) ? sh[t-off] : 0; __syncthreads();
        sh[t] += x; __syncthreads();
    }
    if (i < NV) g_off[i] = sh[t] - v;
    if (t == 1023) g_bsum[blockIdx.x] = sh[1023];
}

// finalize offsets/cursor/norm AND scale feats -> tA16 (fp16); inline block-sum prefix
__global__ void k_scan3t0(const float* __restrict__ feats){
    __shared__ float snorm[256];
    __shared__ int sboff;
    int t = threadIdx.x;
    int i = blockIdx.x*256 + t;
    int chunk = blockIdx.x >> 2;
    if (t < 32){
        int s = 0;
        for (int j = t; j < chunk; j += 32) s += g_bsum[j];
        #pragma unroll
        for (int o=16;o;o>>=1) s += __shfl_xor_sync(0xffffffffu, s, o);
        if (t == 0) sboff = s;
    }
    __syncthreads();
    if (i < NV){
        int o = g_off[i] + sboff;
        g_off[i] = o; g_cur[i] = o;
        int d = g_deg[i];
        float nv = rsqrtf((float)(d > 1 ? d : 1));
        g_norm[i] = nv;
        snorm[t]  = nv;
    }
    __syncthreads();
    int base4 = blockIdx.x*256*16;
    for (int tt = t; tt < 256*16; tt += 256){
        int r = tt >> 4;
        if (blockIdx.x*256 + r < NV){
            float4 v = __ldg(((const float4*)feats) + base4 + tt);
            float nv = snorm[r];
            uint2 o;
            *(__half2*)&o.x = __floats2half2_rn(v.x*nv, v.y*nv);
            *(__half2*)&o.y = __floats2half2_rn(v.z*nv, v.w*nv);
            g_tA16[base4 + tt] = o;
        }
    }
}

__global__ void k_place(const int* __restrict__ src, const int* __restrict__ dst){
    int e = blockIdx.x*256 + threadIdx.x;
    if (e < NE){
        int p = atomicAdd(&g_cur[dst[e]], 1);
        g_csc[p] = src[e];
    }
}

// hop: warp per node; half-warp per neighbor, 8B (4 halves) per lane -> 128B/row = 1 L2 line
__global__ void k_hop(int sel, int coff, int wt){
    int gw   = (blockIdx.x*blockDim.x + threadIdx.x) >> 5;
    int lane = threadIdx.x & 31;
    if (gw >= NV) return;
    const uint2* tin  = sel ? g_tB16 : g_tA16;
    uint2*       tout = sel ? g_tA16 : g_tB16;
    int s = g_off[gw], e = s + g_deg[gw];
    int half = lane >> 4;
    int c4   = lane & 15;
    float ax=0.f, ay=0.f, az=0.f, aw=0.f;
    int i = s;
    for (; i + 7 < e; i += 8){
        int u0 = g_csc[i + half];
        int u1 = g_csc[i + 2 + half];
        int u2 = g_csc[i + 4 + half];
        int u3 = g_csc[i + 6 + half];
        uint2 w0 = __ldg(&tin[u0*16 + c4]);
        uint2 w1 = __ldg(&tin[u1*16 + c4]);
        uint2 w2 = __ldg(&tin[u2*16 + c4]);
        uint2 w3 = __ldg(&tin[u3*16 + c4]);
        float2 a0 = __half22float2(*(__half2*)&w0.x), b0 = __half22float2(*(__half2*)&w0.y);
        float2 a1 = __half22float2(*(__half2*)&w1.x), b1 = __half22float2(*(__half2*)&w1.y);
        float2 a2 = __half22float2(*(__half2*)&w2.x), b2 = __half22float2(*(__half2*)&w2.y);
        float2 a3 = __half22float2(*(__half2*)&w3.x), b3 = __half22float2(*(__half2*)&w3.y);
        ax += (a0.x + a1.x) + (a2.x + a3.x);
        ay += (a0.y + a1.y) + (a2.y + a3.y);
        az += (b0.x + b1.x) + (b2.x + b3.x);
        aw += (b0.y + b1.y) + (b2.y + b3.y);
    }
    for (; i + 1 < e; i += 2){
        int u = g_csc[i + half];
        uint2 w = __ldg(&tin[u*16 + c4]);
        float2 a = __half22float2(*(__half2*)&w.x), b = __half22float2(*(__half2*)&w.y);
        ax += a.x; ay += a.y; az += b.x; aw += b.y;
    }
    if (i < e && half == 0){
        int u = g_csc[i];
        uint2 w = __ldg(&tin[u*16 + c4]);
        float2 a = __half22float2(*(__half2*)&w.x), b = __half22float2(*(__half2*)&w.y);
        ax += a.x; ay += a.y; az += b.x; aw += b.y;
    }
    ax += __shfl_xor_sync(0xffffffffu, ax, 16);
    ay += __shfl_xor_sync(0xffffffffu, ay, 16);
    az += __shfl_xor_sync(0xffffffffu, az, 16);
    aw += __shfl_xor_sync(0xffffffffu, aw, 16);
    if (half == 0){
        float nv = g_norm[gw];
        float hx = ax*nv, hy = ay*nv, hz = az*nv, hw = aw*nv;
        ((float4*)(g_H + (size_t)gw*ZD + coff))[c4] = make_float4(hx, hy, hz, hw);
        if (wt){
            uint2 o;
            *(__half2*)&o.x = __floats2half2_rn(hx*nv, hy*nv);
            *(__half2*)&o.y = __floats2half2_rn(hz*nv, hw*nv);
            tout[gw*16 + c4] = o;
        }
    }
}

// symmetric Gram: 512 threads, warp-uniform 32x16 tiles of upper triangle
__global__ void __launch_bounds__(512,1) k_gram(){
    __shared__ __align__(16) float zs[64*ZD];   // 48KB
    int tid = threadIdx.x;
    int w = tid >> 5, lane = tid & 31;
    int nt = (w < 10) ? 3 : 2;                  // 42 = 10*3 + 6*2
    int rowb[3], colb[3];
    #pragma unroll
    for (int k=0;k<3;k++){
        int t = w + 16*k;
        if (t < 42){ rowb[k] = c_tI[t]*32 + lane; colb[k] = c_tJ[t]*16; }
        else       { rowb[k] = 0;                colb[k] = 0; }
    }
    ull acc[3][8];
    #pragma unroll
    for (int k=0;k<3;k++){
        #pragma unroll
        for (int m=0;m<8;m++) acc[k][m] = 0ULL;
    }
    float csacc = 0.f;

    int ntile = (NV + 63) >> 6;
    for (int tile = blockIdx.x; tile < ntile; tile += gridDim.x){
        int r0 = tile << 6;
        int valid = NV - r0; if (valid > 64) valid = 64;
        for (int t = tid; t < 64*ZD/4; t += 512){
            int r = t / (ZD/4);
            float4 v = (r < valid) ? __ldg(((const float4*)(g_H + (size_t)r0*ZD)) + t)
                                   : make_float4(0.f,0.f,0.f,0.f);
            ((float4*)zs)[t] = v;
        }
        __syncthreads();
        #pragma unroll
        for (int k=0;k<3;k++){
            if (k >= nt) break;
            int rb = rowb[k], cb = colb[k];
            #pragma unroll 4
            for (int r=0; r<64; r++){
                const float* row = zs + r*ZD;
                float zi = row[rb];
                ull zz = pack2(zi, zi);
                ulonglong2 p0 = *(const ulonglong2*)(row + cb);
                ulonglong2 p1 = *(const ulonglong2*)(row + cb + 4);
                ulonglong2 p2 = *(const ulonglong2*)(row + cb + 8);
                ulonglong2 p3 = *(const ulonglong2*)(row + cb + 12);
                fma2(acc[k][0], zz, p0.x); fma2(acc[k][1], zz, p0.y);
                fma2(acc[k][2], zz, p1.x); fma2(acc[k][3], zz, p1.y);
                fma2(acc[k][4], zz, p2.x); fma2(acc[k][5], zz, p2.y);
                fma2(acc[k][6], zz, p3.x); fma2(acc[k][7], zz, p3.y);
            }
        }
        if (tid < ZD){
            float s = 0.f;
            #pragma unroll 8
            for (int r=0; r<64; r++) s += zs[r*ZD + tid];
            csacc += s;
        }
        __syncthreads();
    }
    #pragma unroll
    for (int k=0;k<3;k++){
        if (k >= nt) break;
        int rb = rowb[k], cb = colb[k];
        #pragma unroll
        for (int m=0;m<8;m++){
            float2 p = unpack2(acc[k][m]);
            atomicAdd(&g_S[rb*ZD + cb + 2*m],     p.x);
            atomicAdd(&g_S[rb*ZD + cb + 2*m + 1], p.y);
        }
    }
    if (tid < ZD) atomicAdd(&g_cs[tid], csacc);
}

// BN stats per output channel (reads upper triangle of S); fold with q
__global__ void k_stats(const float* __restrict__ gamma, const float* __restrict__ beta,
                        const float* __restrict__ q){
    __shared__ float m[ZD], r1[ZD], r2[ZD];
    int ko = blockIdx.x, t = threadIdx.x;
    m[t] = g_M[ko*ZD + t];
    __syncthreads();
    float w = 0.f;
    #pragma unroll 4
    for (int j=0;j<ZD;j++){
        float sv = (j >= t) ? g_S[t*ZD + j] : g_S[j*ZD + t];
        w = fmaf(sv, m[j], w);
    }
    r1[t] = m[t]*w;
    r2[t] = m[t]*g_cs[t];
    __syncthreads();
    for (int s=96; s>=3; s>>=1){
        if (t < s){ r1[t] += r1[t+s]; r2[t] += r2[t+s]; }
        __syncthreads();
    }
    if (t == 0){
        float qf  = r1[0]+r1[1]+r1[2];
        float mz  = (r2[0]+r2[1]+r2[2]) * (1.0f/NV);
        float var = qf*(1.0f/NV) - mz*mz;
        float c   = g_cv[ko];
        float inv = rsqrtf(var + EPS);
        float sc  = gamma[ko]*inv;
        float tsh = beta[ko] - (mz + c)*sc;
        float qk  = q[ko >> 6];
        g_av[ko] = qk*sc;
        g_dt[ko] = qk*(sc*c + tsh);
    }
}

__global__ void k_vk(){
    int idx = blockIdx.x*256 + threadIdx.x;
    if (idx < ZD*OD){
        int i = idx >> 6, o = idx & 63;
        float s = 0.f;
        #pragma unroll
        for (int k=0;k<8;k++){ int ko = k*64+o; s = fmaf(g_av[ko], g_M[ko*ZD + i], s); }
        g_V[idx] = s;
    } else if (idx < ZD*OD + OD){
        int o = idx - ZD*OD;
        float s = 0.f;
        #pragma unroll
        for (int k=0;k<8;k++) s += g_dt[k*64+o];
        g_dc[o] = s;
    }
}

// out = H @ V^T + dconst ; 128 rows/block, thread = 4 rows x 8 cols
__global__ void __launch_bounds__(256) k_out(float* __restrict__ out){
    __shared__ float Vs[32*64];
    __shared__ float zs[128*33];
    int tid = threadIdx.x;
    int tc = tid & 7, tr = tid >> 3;
    int r0 = blockIdx.x * 128;
    int valid = NV - r0; if (valid > 128) valid = 128;

    ull acc[4][4];
    #pragma unroll
    for (int a=0;a<4;a++){
        #pragma unroll
        for (int b=0;b<4;b++) acc[a][b] = 0ULL;
    }

    for (int kk=0; kk<ZD; kk+=32){
        for (int t = tid; t < 512; t += 256)
            ((float4*)Vs)[t] = __ldg(((const float4*)(g_V + kk*64)) + t);
        for (int t = tid; t < 1024; t += 256){
            int r = t >> 3, c = t & 7;
            float4 v = (r < valid)
                ? __ldg((const float4*)(g_H + (size_t)(r0+r)*ZD + kk) + c)
                : make_float4(0.f,0.f,0.f,0.f);
            float* d = zs + r*33 + c*4;
            d[0]=v.x; d[1]=v.y; d[2]=v.z; d[3]=v.w;
        }
        __syncthreads();
        #pragma unroll 4
        for (int k=0;k<32;k++){
            ull vv[4];
            #pragma unroll
            for (int c=0;c<4;c++) vv[c] = ((const ull*)(Vs + k*64))[tc*4 + c];
            #pragma unroll
            for (int rr=0;rr<4;rr++){
                float z = zs[(tr*4+rr)*33 + k];
                ull zz = pack2(z, z);
                #pragma unroll
                for (int c=0;c<4;c++) fma2(acc[rr][c], zz, vv[c]);
            }
        }
        __syncthreads();
    }
    #pragma unroll
    for (int rr=0;rr<4;rr++){
        int row = r0 + tr*4 + rr;
        if (row < NV){
            float2* o2 = (float2*)(out + (size_t)row*64 + tc*8);
            #pragma unroll
            for (int c=0;c<4;c++){
                float2 p = unpack2(acc[rr][c]);
                p.x += g_dc[tc*8 + 2*c];
                p.y += g_dc[tc*8 + 2*c + 1];
                o2[c] = p;
            }
        }
    }
}

extern "C" void kernel_launch(void* const* d_in, const int* in_sizes, int n_in,
                              void* d_out, int out_size){
    const float* feats = (const float*)d_in[0];
    const int*   src   = (const int*)  d_in[1];
    const int*   dst   = (const int*)  d_in[2];
    const float* W0    = (const float*)d_in[3];
    const float* b0    = (const float*)d_in[4];
    const float* W1    = (const float*)d_in[5];
    const float* b1    = (const float*)d_in[6];
    const float* W2    = (const float*)d_in[7];
    const float* b2    = (const float*)d_in[8];
    const float* fcW   = (const float*)d_in[9];
    const float* fcb   = (const float*)d_in[10];
    const float* gamma = (const float*)d_in[11];
    const float* beta  = (const float*)d_in[12];
    const float* q     = (const float*)d_in[13];
    float* out = (float*)d_out;

    k_zero   <<<391, 256>>>();
    k_weights<<<387, 256>>>(fcW, W0, W1, W2, b0, b1, b2, fcb);
    k_deg    <<<6250, 256>>>(dst);
    k_scan1  <<<98, 1024>>>();
    k_scan3t0<<<391, 256>>>(feats);
    k_place  <<<6250, 256>>>(src, dst);
    k_hop    <<<12500, 256>>>(0, 0,   1);
    k_hop    <<<12500, 256>>>(1, 64,  1);
    k_hop    <<<12500, 256>>>(0, 128, 0);
    k_gram   <<<148, 512>>>();
    k_stats  <<<512, 192>>>(gamma, beta, q);
    k_vk     <<<49, 256>>>();
    k_out    <<<782, 256>>>(out);
}

// round 11
// speedup vs baseline: 1.4074x; 1.0119x over previous
#include <cuda_runtime.h>
#include <cuda_fp16.h>

#define NV 100000
#define NE 1600000
#define CSCP 2400000            // NE + 8*NV (padded CSC)
#define ZD 192
#define HD 512
#define OD 64
#define EPS 1e-5f

typedef unsigned long long ull;

__device__ __forceinline__ ull pack2(float lo, float hi){
    ull r; asm("mov.b64 %0, {%1,%2};" : "=l"(r) : "f"(lo), "f"(hi)); return r;
}
__device__ __forceinline__ void fma2(ull &d, ull a, ull b){
    asm("fma.rn.f32x2 %0, %1, %2, %0;" : "+l"(d) : "l"(a), "l"(b));
}
__device__ __forceinline__ float2 unpack2(ull v){
    float2 f; asm("mov.b64 {%0,%1}, %2;" : "=f"(f.x), "=f"(f.y) : "l"(v)); return f;
}

// symmetric gram tile list: S tiled (32 rows x 16 cols); keep J >= 2I  (42 tiles)
__constant__ unsigned char c_tI[42] = {0,0,0,0,0,0,0,0,0,0,0,0,
                                       1,1,1,1,1,1,1,1,1,1,
                                       2,2,2,2,2,2,2,2,
                                       3,3,3,3,3,3,
                                       4,4,4,4,
                                       5,5};
__constant__ unsigned char c_tJ[42] = {0,1,2,3,4,5,6,7,8,9,10,11,
                                       2,3,4,5,6,7,8,9,10,11,
                                       4,5,6,7,8,9,10,11,
                                       6,7,8,9,10,11,
                                       8,9,10,11,
                                       10,11};

// scratch (no allocations allowed)
__device__ int   g_deg[NV];
__device__ int   g_off[NV];
__device__ int   g_csc[CSCP];
__device__ float g_norm[NV];
__device__ uint2 g_tA16[(NV+1)*16];    // fp16 t, 64 halves/row; row NV = zeros (pad target)
__device__ uint2 g_tB16[(NV+1)*16];
__device__ uint2 g_H16[(size_t)NV*48]; // fp16 H: 192 halves/row
__device__ float g_S[ZD*ZD];           // Gram (upper triangle authoritative)
__device__ float g_cs[ZD];             // column sums
__device__ float g_M[HD*ZD];           // folded weights
__device__ float g_cv[HD];             // folded bias
__device__ float g_av[HD];             // q*gamma*invstd
__device__ float g_dt[HD];             // per-channel const
__device__ float g_V[ZD*OD];
__device__ float g_dc[OD];
__device__ int   g_bsum[128];

// zero/init everything that is accumulated or pad-read; fill CSC with dummy index NV
__global__ void k_zero(){
    int i = blockIdx.x*256 + threadIdx.x;
    if (i < CSCP)  g_csc[i] = NV;
    if (i < NV)    g_deg[i] = 0;
    if (i < ZD*ZD) g_S[i]   = 0.f;
    if (i < ZD)    g_cs[i]  = 0.f;
    if (i < 16){
        g_tA16[NV*16 + i] = make_uint2(0u,0u);
        g_tB16[NV*16 + i] = make_uint2(0u,0u);
    }
}

// M_j = fc_W_j @ W_j ; c = fc_W @ [b0;b1;b2] + fc_b
__global__ void k_weights(const float* __restrict__ fcW,
                          const float* __restrict__ W0, const float* __restrict__ W1,
                          const float* __restrict__ W2,
                          const float* __restrict__ b0, const float* __restrict__ b1,
                          const float* __restrict__ b2, const float* __restrict__ fcb){
    int idx = blockIdx.x*256 + threadIdx.x;
    if (idx < HD*ZD){
        int ko = idx / ZD, i = idx - ko*ZD;
        int j = i >> 6, d = i & 63;
        const float* W  = (j==0)?W0:((j==1)?W1:W2);
        const float* fr = fcW + ko*1536 + j*512;
        float s = 0.f;
        #pragma unroll 4
        for (int h=0; h<HD; h++) s = fmaf(fr[h], W[h*64+d], s);
        g_M[ko*ZD+i] = s;
    } else if (idx < HD*ZD + HD){
        int ko = idx - HD*ZD;
        const float* fr = fcW + ko*1536;
        float s = fcb[ko];
        for (int h=0; h<HD; h++)
            s += fr[h]*b0[h] + fr[512+h]*b1[h] + fr[1024+h]*b2[h];
        g_cv[ko] = s;
    }
}

__global__ void k_deg(const int* __restrict__ dst){
    int e = blockIdx.x*256 + threadIdx.x;
    if (e < NE) atomicAdd(&g_deg[dst[e]], 1);
}

// scan of PADDED degrees ((d+7)&~7) -> 8-aligned slot starts
__global__ void k_scan1(){
    __shared__ int sh[1024];
    int t = threadIdx.x, i = blockIdx.x*1024 + t;
    int d = (i < NV) ? g_deg[i] : 0;
    int v = (d + 7) & ~7;
    sh[t] = v; __syncthreads();
    for (int off=1; off<1024; off<<=1){
        int x = (t >= off) ? sh[t-off] : 0; __syncthreads();
        sh[t] += x; __syncthreads();
    }
    if (i < NV) g_off[i] = sh[t] - v;
    if (t == 1023) g_bsum[blockIdx.x] = sh[1023];
}

// finalize slot starts/norm AND scale feats -> tA16 (fp16); inline block-sum prefix
__global__ void k_scan3t0(const float* __restrict__ feats){
    __shared__ float snorm[256];
    __shared__ int sboff;
    int t = threadIdx.x;
    int i = blockIdx.x*256 + t;
    int chunk = blockIdx.x >> 2;
    if (t < 32){
        int s = 0;
        for (int j = t; j < chunk; j += 32) s += g_bsum[j];
        #pragma unroll
        for (int o=16;o;o>>=1) s += __shfl_xor_sync(0xffffffffu, s, o);
        if (t == 0) sboff = s;
    }
    __syncthreads();
    if (i < NV){
        g_off[i] += sboff;                 // 8-aligned slot start; k_place bumps this
        int d = g_deg[i];
        float nv = rsqrtf((float)(d > 1 ? d : 1));
        g_norm[i] = nv;
        snorm[t]  = nv;
    }
    __syncthreads();
    int base4 = blockIdx.x*256*16;
    for (int tt = t; tt < 256*16; tt += 256){
        int r = tt >> 4;
        if (blockIdx.x*256 + r < NV){
            float4 v = __ldg(((const float4*)feats) + base4 + tt);
            float nv = snorm[r];
            uint2 o;
            *(__half2*)&o.x = __floats2half2_rn(v.x*nv, v.y*nv);
            *(__half2*)&o.y = __floats2half2_rn(v.z*nv, v.w*nv);
            g_tA16[base4 + tt] = o;
        }
    }
}

// place edges; cursor is g_off itself (ends at start+deg; hop recovers start = off-deg)
__global__ void k_place(const int* __restrict__ src, const int* __restrict__ dst){
    int e = blockIdx.x*256 + threadIdx.x;
    if (e < NE){
        int p = atomicAdd(&g_off[dst[e]], 1);
        g_csc[p] = src[e];
    }
}

// hop: warp per node; uniform ceil(deg/8) iters; per half-warp: 1 int4 index load + 4 gathers
__global__ void k_hop(int sel, int coff16, int wt){
    int gw   = (blockIdx.x*blockDim.x + threadIdx.x) >> 5;
    int lane = threadIdx.x & 31;
    if (gw >= NV) return;
    const uint2* tin  = sel ? g_tB16 : g_tA16;
    uint2*       tout = sel ? g_tA16 : g_tB16;
    int dv = g_deg[gw];
    int s  = g_off[gw] - dv;           // 8-aligned slot start
    int niter = (dv + 7) >> 3;
    int half = lane >> 4;
    int c4   = lane & 15;
    float ax=0.f, ay=0.f, az=0.f, aw=0.f;
    const int* base = g_csc + s + half*4;
    for (int it = 0; it < niter; it++){
        int4 u = *(const int4*)(base + it*8);       // 16B-aligned broadcast
        uint2 w0 = __ldg(&tin[u.x*16 + c4]);
        uint2 w1 = __ldg(&tin[u.y*16 + c4]);
        uint2 w2 = __ldg(&tin[u.z*16 + c4]);
        uint2 w3 = __ldg(&tin[u.w*16 + c4]);
        float2 a0 = __half22float2(*(__half2*)&w0.x), b0 = __half22float2(*(__half2*)&w0.y);
        float2 a1 = __half22float2(*(__half2*)&w1.x), b1 = __half22float2(*(__half2*)&w1.y);
        float2 a2 = __half22float2(*(__half2*)&w2.x), b2 = __half22float2(*(__half2*)&w2.y);
        float2 a3 = __half22float2(*(__half2*)&w3.x), b3 = __half22float2(*(__half2*)&w3.y);
        ax += (a0.x + a1.x) + (a2.x + a3.x);
        ay += (a0.y + a1.y) + (a2.y + a3.y);
        az += (b0.x + b1.x) + (b2.x + b3.x);
        aw += (b0.y + b1.y) + (b2.y + b3.y);
    }
    ax += __shfl_xor_sync(0xffffffffu, ax, 16);
    ay += __shfl_xor_sync(0xffffffffu, ay, 16);
    az += __shfl_xor_sync(0xffffffffu, az, 16);
    aw += __shfl_xor_sync(0xffffffffu, aw, 16);
    if (half == 0){
        float nv = g_norm[gw];
        float hx = ax*nv, hy = ay*nv, hz = az*nv, hw = aw*nv;
        uint2 hh;
        *(__half2*)&hh.x = __floats2half2_rn(hx, hy);
        *(__half2*)&hh.y = __floats2half2_rn(hz, hw);
        g_H16[(size_t)gw*48 + coff16 + c4] = hh;
        if (wt){
            uint2 o;
            *(__half2*)&o.x = __floats2half2_rn(hx*nv, hy*nv);
            *(__half2*)&o.y = __floats2half2_rn(hz*nv, hw*nv);
            tout[gw*16 + c4] = o;
        }
    }
}

// symmetric Gram: 512 threads, warp-uniform 32x16 tiles of upper triangle; H16 -> fp32 smem
__global__ void __launch_bounds__(512,1) k_gram(){
    __shared__ __align__(16) float zs[64*ZD];   // 48KB
    int tid = threadIdx.x;
    int w = tid >> 5, lane = tid & 31;
    int nt = (w < 10) ? 3 : 2;                  // 42 = 10*3 + 6*2
    int rowb[3], colb[3];
    #pragma unroll
    for (int k=0;k<3;k++){
        int t = w + 16*k;
        if (t < 42){ rowb[k] = c_tI[t]*32 + lane; colb[k] = c_tJ[t]*16; }
        else       { rowb[k] = 0;                colb[k] = 0; }
    }
    ull acc[3][8];
    #pragma unroll
    for (int k=0;k<3;k++){
        #pragma unroll
        for (int m=0;m<8;m++) acc[k][m] = 0ULL;
    }
    float csacc = 0.f;

    int ntile = (NV + 63) >> 6;
    for (int tile = blockIdx.x; tile < ntile; tile += gridDim.x){
        int r0 = tile << 6;
        int valid = NV - r0; if (valid > 64) valid = 64;
        for (int t = tid; t < 64*48; t += 512){
            int r = t / 48, c = t - r*48;
            uint2 wv = (r < valid) ? __ldg(&g_H16[(size_t)(r0+r)*48 + c])
                                   : make_uint2(0u,0u);
            float2 a = __half22float2(*(__half2*)&wv.x);
            float2 b = __half22float2(*(__half2*)&wv.y);
            *(float4*)&zs[r*ZD + c*4] = make_float4(a.x, a.y, b.x, b.y);
        }
        __syncthreads();
        #pragma unroll
        for (int k=0;k<3;k++){
            if (k >= nt) break;
            int rb = rowb[k], cb = colb[k];
            #pragma unroll 4
            for (int r=0; r<64; r++){
                const float* row = zs + r*ZD;
                float zi = row[rb];
                ull zz = pack2(zi, zi);
                ulonglong2 p0 = *(const ulonglong2*)(row + cb);
                ulonglong2 p1 = *(const ulonglong2*)(row + cb + 4);
                ulonglong2 p2 = *(const ulonglong2*)(row + cb + 8);
                ulonglong2 p3 = *(const ulonglong2*)(row + cb + 12);
                fma2(acc[k][0], zz, p0.x); fma2(acc[k][1], zz, p0.y);
                fma2(acc[k][2], zz, p1.x); fma2(acc[k][3], zz, p1.y);
                fma2(acc[k][4], zz, p2.x); fma2(acc[k][5], zz, p2.y);
                fma2(acc[k][6], zz, p3.x); fma2(acc[k][7], zz, p3.y);
            }
        }
        if (tid < ZD){
            float s = 0.f;
            #pragma unroll 8
            for (int r=0; r<64; r++) s += zs[r*ZD + tid];
            csacc += s;
        }
        __syncthreads();
    }
    #pragma unroll
    for (int k=0;k<3;k++){
        if (k >= nt) break;
        int rb = rowb[k], cb = colb[k];
        #pragma unroll
        for (int m=0;m<8;m++){
            float2 p = unpack2(acc[k][m]);
            atomicAdd(&g_S[rb*ZD + cb + 2*m],     p.x);
            atomicAdd(&g_S[rb*ZD + cb + 2*m + 1], p.y);
        }
    }
    if (tid < ZD) atomicAdd(&g_cs[tid], csacc);
}

// BN stats per output channel (reads upper triangle of S); fold with q
__global__ void k_stats(const float* __restrict__ gamma, const float* __restrict__ beta,
                        const float* __restrict__ q){
    __shared__ float m[ZD], r1[ZD], r2[ZD];
    int ko = blockIdx.x, t = threadIdx.x;
    m[t] = g_M[ko*ZD + t];
    __syncthreads();
    float w = 0.f;
    #pragma unroll 4
    for (int j=0;j<ZD;j++){
        float sv = (j >= t) ? g_S[t*ZD + j] : g_S[j*ZD + t];
        w = fmaf(sv, m[j], w);
    }
    r1[t] = m[t]*w;
    r2[t] = m[t]*g_cs[t];
    __syncthreads();
    for (int s=96; s>=3; s>>=1){
        if (t < s){ r1[t] += r1[t+s]; r2[t] += r2[t+s]; }
        __syncthreads();
    }
    if (t == 0){
        float qf  = r1[0]+r1[1]+r1[2];
        float mz  = (r2[0]+r2[1]+r2[2]) * (1.0f/NV);
        float var = qf*(1.0f/NV) - mz*mz;
        float c   = g_cv[ko];
        float inv = rsqrtf(var + EPS);
        float sc  = gamma[ko]*inv;
        float tsh = beta[ko] - (mz + c)*sc;
        float qk  = q[ko >> 6];
        g_av[ko] = qk*sc;
        g_dt[ko] = qk*(sc*c + tsh);
    }
}

__global__ void k_vk(){
    int idx = blockIdx.x*256 + threadIdx.x;
    if (idx < ZD*OD){
        int i = idx >> 6, o = idx & 63;
        float s = 0.f;
        #pragma unroll
        for (int k=0;k<8;k++){ int ko = k*64+o; s = fmaf(g_av[ko], g_M[ko*ZD + i], s); }
        g_V[idx] = s;
    } else if (idx < ZD*OD + OD){
        int o = idx - ZD*OD;
        float s = 0.f;
        #pragma unroll
        for (int k=0;k<8;k++) s += g_dt[k*64+o];
        g_dc[o] = s;
    }
}

// out = H @ V^T + dconst ; 128 rows/block, thread = 4 rows x 8 cols; H16 -> fp32 smem
__global__ void __launch_bounds__(256) k_out(float* __restrict__ out){
    __shared__ float Vs[32*64];
    __shared__ float zs[128*33];
    int tid = threadIdx.x;
    int tc = tid & 7, tr = tid >> 3;
    int r0 = blockIdx.x * 128;
    int valid = NV - r0; if (valid > 128) valid = 128;

    ull acc[4][4];
    #pragma unroll
    for (int a=0;a<4;a++){
        #pragma unroll
        for (int b=0;b<4;b++) acc[a][b] = 0ULL;
    }

    for (int kk=0; kk<ZD; kk+=32){
        for (int t = tid; t < 512; t += 256)
            ((float4*)Vs)[t] = __ldg(((const float4*)(g_V + kk*64)) + t);
        for (int t = tid; t < 1024; t += 256){
            int r = t >> 3, c = t & 7;
            uint2 wv = (r < valid)
                ? __ldg(&g_H16[(size_t)(r0+r)*48 + (kk>>2) + c])
                : make_uint2(0u,0u);
            float2 a = __half22float2(*(__half2*)&wv.x);
            float2 b = __half22float2(*(__half2*)&wv.y);
            float* d = zs + r*33 + c*4;
            d[0]=a.x; d[1]=a.y; d[2]=b.x; d[3]=b.y;
        }
        __syncthreads();
        #pragma unroll 4
        for (int k=0;k<32;k++){
            ull vv[4];
            #pragma unroll
            for (int c=0;c<4;c++) vv[c] = ((const ull*)(Vs + k*64))[tc*4 + c];
            #pragma unroll
            for (int rr=0;rr<4;rr++){
                float z = zs[(tr*4+rr)*33 + k];
                ull zz = pack2(z, z);
                #pragma unroll
                for (int c=0;c<4;c++) fma2(acc[rr][c], zz, vv[c]);
            }
        }
        __syncthreads();
    }
    #pragma unroll
    for (int rr=0;rr<4;rr++){
        int row = r0 + tr*4 + rr;
        if (row < NV){
            float2* o2 = (float2*)(out + (size_t)row*64 + tc*8);
            #pragma unroll
            for (int c=0;c<4;c++){
                float2 p = unpack2(acc[rr][c]);
                p.x += g_dc[tc*8 + 2*c];
                p.y += g_dc[tc*8 + 2*c + 1];
                o2[c] = p;
            }
        }
    }
}

extern "C" void kernel_launch(void* const* d_in, const int* in_sizes, int n_in,
                              void* d_out, int out_size){
    const float* feats = (const float*)d_in[0];
    const int*   src   = (const int*)  d_in[1];
    const int*   dst   = (const int*)  d_in[2];
    const float* W0    = (const float*)d_in[3];
    const float* b0    = (const float*)d_in[4];
    const float* W1    = (const float*)d_in[5];
    const float* b1    = (const float*)d_in[6];
    const float* W2    = (const float*)d_in[7];
    const float* b2    = (const float*)d_in[8];
    const float* fcW   = (const float*)d_in[9];
    const float* fcb   = (const float*)d_in[10];
    const float* gamma = (const float*)d_in[11];
    const float* beta  = (const float*)d_in[12];
    const float* q     = (const float*)d_in[13];
    float* out = (float*)d_out;

    k_zero   <<<9375, 256>>>();                                   // #1
    k_deg    <<<6250, 256>>>(dst);                                // #2
    k_scan1  <<<98, 1024>>>();                                    // #3
    k_weights<<<387, 256>>>(fcW, W0, W1, W2, b0, b1, b2, fcb);    // #4  <- profiled slot
    k_scan3t0<<<391, 256>>>(feats);                               // #5
    k_place  <<<6250, 256>>>(src, dst);                           // #6
    k_hop    <<<12500, 256>>>(0, 0,  1);                          // #7
    k_hop    <<<12500, 256>>>(1, 16, 1);                          // #8
    k_hop    <<<12500, 256>>>(0, 32, 0);                          // #9
    k_gram   <<<148, 512>>>();                                    // #10
    k_stats  <<<512, 192>>>(gamma, beta, q);                      // #11
    k_vk     <<<49, 256>>>();                                     // #12
    k_out    <<<782, 256>>>(out);                                 // #13
}

// round 12
// speedup vs baseline: 1.9689x; 1.3990x over previous
#include <cuda_runtime.h>
#include <cuda_fp16.h>

#define NV 100000
#define NE 1600000
#define CSCP 2400000            // NE + 8*NV (padded CSC)
#define ZD 192
#define HD 512
#define OD 64
#define EPS 1e-5f

typedef unsigned long long ull;

__device__ __forceinline__ ull pack2(float lo, float hi){
    ull r; asm("mov.b64 %0, {%1,%2};" : "=l"(r) : "f"(lo), "f"(hi)); return r;
}
__device__ __forceinline__ void fma2(ull &d, ull a, ull b){
    asm("fma.rn.f32x2 %0, %1, %2, %0;" : "+l"(d) : "l"(a), "l"(b));
}
__device__ __forceinline__ float2 unpack2(ull v){
    float2 f; asm("mov.b64 {%0,%1}, %2;" : "=f"(f.x), "=f"(f.y) : "l"(v)); return f;
}

// symmetric gram tile list: S tiled (32 rows x 16 cols); keep J >= 2I  (42 tiles)
__constant__ unsigned char c_tI[42] = {0,0,0,0,0,0,0,0,0,0,0,0,
                                       1,1,1,1,1,1,1,1,1,1,
                                       2,2,2,2,2,2,2,2,
                                       3,3,3,3,3,3,
                                       4,4,4,4,
                                       5,5};
__constant__ unsigned char c_tJ[42] = {0,1,2,3,4,5,6,7,8,9,10,11,
                                       2,3,4,5,6,7,8,9,10,11,
                                       4,5,6,7,8,9,10,11,
                                       6,7,8,9,10,11,
                                       8,9,10,11,
                                       10,11};

// scratch (no allocations allowed)
__device__ int   g_deg[NV];
__device__ int   g_off[NV];
__device__ int   g_csc[CSCP];
__device__ float g_norm[NV];
__device__ uint2 g_tA16[(NV+1)*16];    // fp16 t, 64 halves/row; row NV = zeros (pad target)
__device__ uint2 g_tB16[(NV+1)*16];
__device__ uint2 g_H16[(size_t)NV*48]; // fp16 H: 192 halves/row
__device__ float g_S[ZD*ZD];           // Gram (upper triangle authoritative)
__device__ float g_cs[ZD];             // column sums
__device__ float g_M[HD*ZD];           // folded weights (atomically accumulated)
__device__ float g_cv[HD];             // folded bias
__device__ float g_av[HD];             // q*gamma*invstd
__device__ float g_dt[HD];             // per-channel const
__device__ float g_V[ZD*OD];
__device__ float g_dc[OD];
__device__ int   g_bsum[128];

// zero/init everything that is accumulated or pad-read; fill CSC with dummy index NV
__global__ void k_zero(){
    int i = blockIdx.x*256 + threadIdx.x;
    if (i < CSCP)  g_csc[i] = NV;
    if (i < NV)    g_deg[i] = 0;
    if (i < HD*ZD) g_M[i]   = 0.f;
    if (i < ZD*ZD) g_S[i]   = 0.f;
    if (i < ZD)    g_cs[i]  = 0.f;
    if (i < 16){
        g_tA16[NV*16 + i] = make_uint2(0u,0u);
        g_tB16[NV*16 + i] = make_uint2(0u,0u);
    }
}

// folded-weight GEMM: M[ko, j*64+d] += sum_{k0..k0+63} fcW[ko, j*512+k] * Wj[k, d]
// grid = 8 ko-tiles x 3 j x 8 K-chunks = 192 blocks; 64x64 tile, 4x4 per thread
__global__ void __launch_bounds__(256) k_wgemm(const float* __restrict__ fcW,
                          const float* __restrict__ W0, const float* __restrict__ W1,
                          const float* __restrict__ W2){
    __shared__ float As[64][68];      // fcW tile [ko][k]
    __shared__ float Bs[64][64];      // W tile  [k][d]
    int b = blockIdx.x;
    int mt = b & 7;                   // ko tile
    int j  = (b >> 3) % 3;            // hop index
    int kc = b / 24;                  // K chunk
    int ko0 = mt << 6, k0 = kc << 6;
    const float* W = (j==0)?W0:((j==1)?W1:W2);
    int tid = threadIdx.x;
    int ty = tid >> 4, tx = tid & 15;

    // stage A: 64x64 floats, coalesced float4
    for (int t = tid; t < 1024; t += 256){
        int r = t >> 4, c4 = (t & 15) << 2;
        float4 v = __ldg((const float4*)(fcW + (size_t)(ko0 + r)*1536 + j*512 + k0 + c4));
        As[r][c4] = v.x; As[r][c4+1] = v.y; As[r][c4+2] = v.z; As[r][c4+3] = v.w;
    }
    // stage B: 64x64 floats
    for (int t = tid; t < 1024; t += 256){
        int r = t >> 4, c4 = (t & 15) << 2;
        float4 v = __ldg((const float4*)(W + (size_t)(k0 + r)*64 + c4));
        *(float4*)&Bs[r][c4] = v;
    }
    __syncthreads();

    float acc[4][4] = {};
    #pragma unroll 8
    for (int k = 0; k < 64; k++){
        float a0 = As[ty*4+0][k];
        float a1 = As[ty*4+1][k];
        float a2 = As[ty*4+2][k];
        float a3 = As[ty*4+3][k];
        float4 bv = *(const float4*)&Bs[k][tx*4];
        acc[0][0]=fmaf(a0,bv.x,acc[0][0]); acc[0][1]=fmaf(a0,bv.y,acc[0][1]);
        acc[0][2]=fmaf(a0,bv.z,acc[0][2]); acc[0][3]=fmaf(a0,bv.w,acc[0][3]);
        acc[1][0]=fmaf(a1,bv.x,acc[1][0]); acc[1][1]=fmaf(a1,bv.y,acc[1][1]);
        acc[1][2]=fmaf(a1,bv.z,acc[1][2]); acc[1][3]=fmaf(a1,bv.w,acc[1][3]);
        acc[2][0]=fmaf(a2,bv.x,acc[2][0]); acc[2][1]=fmaf(a2,bv.y,acc[2][1]);
        acc[2][2]=fmaf(a2,bv.z,acc[2][2]); acc[2][3]=fmaf(a2,bv.w,acc[2][3]);
        acc[3][0]=fmaf(a3,bv.x,acc[3][0]); acc[3][1]=fmaf(a3,bv.y,acc[3][1]);
        acc[3][2]=fmaf(a3,bv.z,acc[3][2]); acc[3][3]=fmaf(a3,bv.w,acc[3][3]);
    }
    #pragma unroll
    for (int r = 0; r < 4; r++){
        int ko = ko0 + ty*4 + r;
        #pragma unroll
        for (int c = 0; c < 4; c++)
            atomicAdd(&g_M[(size_t)ko*ZD + j*64 + tx*4 + c], acc[r][c]);
    }
}

// bias fold: c[ko] = fcb[ko] + fcW[ko]·[b0;b1;b2] ; warp per channel
__global__ void k_wbias(const float* __restrict__ fcW,
                        const float* __restrict__ b0, const float* __restrict__ b1,
                        const float* __restrict__ b2, const float* __restrict__ fcb){
    int w = (blockIdx.x*256 + threadIdx.x) >> 5;
    int lane = threadIdx.x & 31;
    if (w >= HD) return;
    const float* fr = fcW + (size_t)w*1536;
    float s = 0.f;
    #pragma unroll 4
    for (int h = lane; h < HD; h += 32)
        s += fr[h]*b0[h] + fr[512+h]*b1[h] + fr[1024+h]*b2[h];
    #pragma unroll
    for (int o=16;o;o>>=1) s += __shfl_xor_sync(0xffffffffu, s, o);
    if (lane == 0) g_cv[w] = s + fcb[w];
}

__global__ void k_deg(const int* __restrict__ dst){
    int e = blockIdx.x*256 + threadIdx.x;
    if (e < NE) atomicAdd(&g_deg[dst[e]], 1);
}

// scan of PADDED degrees ((d+7)&~7) -> 8-aligned slot starts
__global__ void k_scan1(){
    __shared__ int sh[1024];
    int t = threadIdx.x, i = blockIdx.x*1024 + t;
    int d = (i < NV) ? g_deg[i] : 0;
    int v = (d + 7) & ~7;
    sh[t] = v; __syncthreads();
    for (int off=1; off<1024; off<<=1){
        int x = (t >= off) ? sh[t-off] : 0; __syncthreads();
        sh[t] += x; __syncthreads();
    }
    if (i < NV) g_off[i] = sh[t] - v;
    if (t == 1023) g_bsum[blockIdx.x] = sh[1023];
}

// finalize slot starts/norm AND scale feats -> tA16 (fp16); inline block-sum prefix
__global__ void k_scan3t0(const float* __restrict__ feats){
    __shared__ float snorm[256];
    __shared__ int sboff;
    int t = threadIdx.x;
    int i = blockIdx.x*256 + t;
    int chunk = blockIdx.x >> 2;
    if (t < 32){
        int s = 0;
        for (int j = t; j < chunk; j += 32) s += g_bsum[j];
        #pragma unroll
        for (int o=16;o;o>>=1) s += __shfl_xor_sync(0xffffffffu, s, o);
        if (t == 0) sboff = s;
    }
    __syncthreads();
    if (i < NV){
        g_off[i] += sboff;                 // 8-aligned slot start; k_place bumps this
        int d = g_deg[i];
        float nv = rsqrtf((float)(d > 1 ? d : 1));
        g_norm[i] = nv;
        snorm[t]  = nv;
    }
    __syncthreads();
    int base4 = blockIdx.x*256*16;
    for (int tt = t; tt < 256*16; tt += 256){
        int r = tt >> 4;
        if (blockIdx.x*256 + r < NV){
            float4 v = __ldg(((const float4*)feats) + base4 + tt);
            float nv = snorm[r];
            uint2 o;
            *(__half2*)&o.x = __floats2half2_rn(v.x*nv, v.y*nv);
            *(__half2*)&o.y = __floats2half2_rn(v.z*nv, v.w*nv);
            g_tA16[base4 + tt] = o;
        }
    }
}

// place edges; cursor is g_off itself (ends at start+deg; hop recovers start = off-deg)
__global__ void k_place(const int* __restrict__ src, const int* __restrict__ dst){
    int e = blockIdx.x*256 + threadIdx.x;
    if (e < NE){
        int p = atomicAdd(&g_off[dst[e]], 1);
        g_csc[p] = src[e];
    }
}

// hop: warp per node; uniform ceil(deg/8) iters; per half-warp: 1 int4 index load + 4 gathers
__global__ void k_hop(int sel, int coff16, int wt){
    int gw   = (blockIdx.x*blockDim.x + threadIdx.x) >> 5;
    int lane = threadIdx.x & 31;
    if (gw >= NV) return;
    const uint2* tin  = sel ? g_tB16 : g_tA16;
    uint2*       tout = sel ? g_tA16 : g_tB16;
    int dv = g_deg[gw];
    int s  = g_off[gw] - dv;           // 8-aligned slot start
    int niter = (dv + 7) >> 3;
    int half = lane >> 4;
    int c4   = lane & 15;
    float ax=0.f, ay=0.f, az=0.f, aw=0.f;
    const int* base = g_csc + s + half*4;
    for (int it = 0; it < niter; it++){
        int4 u = *(const int4*)(base + it*8);       // 16B-aligned broadcast
        uint2 w0 = __ldg(&tin[u.x*16 + c4]);
        uint2 w1 = __ldg(&tin[u.y*16 + c4]);
        uint2 w2 = __ldg(&tin[u.z*16 + c4]);
        uint2 w3 = __ldg(&tin[u.w*16 + c4]);
        float2 a0 = __half22float2(*(__half2*)&w0.x), b0 = __half22float2(*(__half2*)&w0.y);
        float2 a1 = __half22float2(*(__half2*)&w1.x), b1 = __half22float2(*(__half2*)&w1.y);
        float2 a2 = __half22float2(*(__half2*)&w2.x), b2 = __half22float2(*(__half2*)&w2.y);
        float2 a3 = __half22float2(*(__half2*)&w3.x), b3 = __half22float2(*(__half2*)&w3.y);
        ax += (a0.x + a1.x) + (a2.x + a3.x);
        ay += (a0.y + a1.y) + (a2.y + a3.y);
        az += (b0.x + b1.x) + (b2.x + b3.x);
        aw += (b0.y + b1.y) + (b2.y + b3.y);
    }
    ax += __shfl_xor_sync(0xffffffffu, ax, 16);
    ay += __shfl_xor_sync(0xffffffffu, ay, 16);
    az += __shfl_xor_sync(0xffffffffu, az, 16);
    aw += __shfl_xor_sync(0xffffffffu, aw, 16);
    if (half == 0){
        float nv = g_norm[gw];
        float hx = ax*nv, hy = ay*nv, hz = az*nv, hw = aw*nv;
        uint2 hh;
        *(__half2*)&hh.x = __floats2half2_rn(hx, hy);
        *(__half2*)&hh.y = __floats2half2_rn(hz, hw);
        g_H16[(size_t)gw*48 + coff16 + c4] = hh;
        if (wt){
            uint2 o;
            *(__half2*)&o.x = __floats2half2_rn(hx*nv, hy*nv);
            *(__half2*)&o.y = __floats2half2_rn(hz*nv, hw*nv);
            tout[gw*16 + c4] = o;
        }
    }
}

// symmetric Gram: 512 threads, warp-uniform 32x16 tiles of upper triangle; H16 -> fp32 smem
__global__ void __launch_bounds__(512,1) k_gram(){
    __shared__ __align__(16) float zs[64*ZD];   // 48KB
    int tid = threadIdx.x;
    int w = tid >> 5, lane = tid & 31;
    int nt = (w < 10) ? 3 : 2;                  // 42 = 10*3 + 6*2
    int rowb[3], colb[3];
    #pragma unroll
    for (int k=0;k<3;k++){
        int t = w + 16*k;
        if (t < 42){ rowb[k] = c_tI[t]*32 + lane; colb[k] = c_tJ[t]*16; }
        else       { rowb[k] = 0;                colb[k] = 0; }
    }
    ull acc[3][8];
    #pragma unroll
    for (int k=0;k<3;k++){
        #pragma unroll
        for (int m=0;m<8;m++) acc[k][m] = 0ULL;
    }
    float csacc = 0.f;

    int ntile = (NV + 63) >> 6;
    for (int tile = blockIdx.x; tile < ntile; tile += gridDim.x){
        int r0 = tile << 6;
        int valid = NV - r0; if (valid > 64) valid = 64;
        for (int t = tid; t < 64*48; t += 512){
            int r = t / 48, c = t - r*48;
            uint2 wv = (r < valid) ? __ldg(&g_H16[(size_t)(r0+r)*48 + c])
                                   : make_uint2(0u,0u);
            float2 a = __half22float2(*(__half2*)&wv.x);
            float2 b = __half22float2(*(__half2*)&wv.y);
            *(float4*)&zs[r*ZD + c*4] = make_float4(a.x, a.y, b.x, b.y);
        }
        __syncthreads();
        #pragma unroll
        for (int k=0;k<3;k++){
            if (k >= nt) break;
            int rb = rowb[k], cb = colb[k];
            #pragma unroll 4
            for (int r=0; r<64; r++){
                const float* row = zs + r*ZD;
                float zi = row[rb];
                ull zz = pack2(zi, zi);
                ulonglong2 p0 = *(const ulonglong2*)(row + cb);
                ulonglong2 p1 = *(const ulonglong2*)(row + cb + 4);
                ulonglong2 p2 = *(const ulonglong2*)(row + cb + 8);
                ulonglong2 p3 = *(const ulonglong2*)(row + cb + 12);
                fma2(acc[k][0], zz, p0.x); fma2(acc[k][1], zz, p0.y);
                fma2(acc[k][2], zz, p1.x); fma2(acc[k][3], zz, p1.y);
                fma2(acc[k][4], zz, p2.x); fma2(acc[k][5], zz, p2.y);
                fma2(acc[k][6], zz, p3.x); fma2(acc[k][7], zz, p3.y);
            }
        }
        if (tid < ZD){
            float s = 0.f;
            #pragma unroll 8
            for (int r=0; r<64; r++) s += zs[r*ZD + tid];
            csacc += s;
        }
        __syncthreads();
    }
    #pragma unroll
    for (int k=0;k<3;k++){
        if (k >= nt) break;
        int rb = rowb[k], cb = colb[k];
        #pragma unroll
        for (int m=0;m<8;m++){
            float2 p = unpack2(acc[k][m]);
            atomicAdd(&g_S[rb*ZD + cb + 2*m],     p.x);
            atomicAdd(&g_S[rb*ZD + cb + 2*m + 1], p.y);
        }
    }
    if (tid < ZD) atomicAdd(&g_cs[tid], csacc);
}

// BN stats per output channel (reads upper triangle of S); fold with q
__global__ void k_stats(const float* __restrict__ gamma, const float* __restrict__ beta,
                        const float* __restrict__ q){
    __shared__ float m[ZD], r1[ZD], r2[ZD];
    int ko = blockIdx.x, t = threadIdx.x;
    m[t] = g_M[ko*ZD + t];
    __syncthreads();
    float w = 0.f;
    #pragma unroll 4
    for (int j=0;j<ZD;j++){
        float sv = (j >= t) ? g_S[t*ZD + j] : g_S[j*ZD + t];
        w = fmaf(sv, m[j], w);
    }
    r1[t] = m[t]*w;
    r2[t] = m[t]*g_cs[t];
    __syncthreads();
    for (int s=96; s>=3; s>>=1){
        if (t < s){ r1[t] += r1[t+s]; r2[t] += r2[t+s]; }
        __syncthreads();
    }
    if (t == 0){
        float qf  = r1[0]+r1[1]+r1[2];
        float mz  = (r2[0]+r2[1]+r2[2]) * (1.0f/NV);
        float var = qf*(1.0f/NV) - mz*mz;
        float c   = g_cv[ko];
        float inv = rsqrtf(var + EPS);
        float sc  = gamma[ko]*inv;
        float tsh = beta[ko] - (mz + c)*sc;
        float qk  = q[ko >> 6];
        g_av[ko] = qk*sc;
        g_dt[ko] = qk*(sc*c + tsh);
    }
}

__global__ void k_vk(){
    int idx = blockIdx.x*256 + threadIdx.x;
    if (idx < ZD*OD){
        int i = idx >> 6, o = idx & 63;
        float s = 0.f;
        #pragma unroll
        for (int k=0;k<8;k++){ int ko = k*64+o; s = fmaf(g_av[ko], g_M[ko*ZD + i], s); }
        g_V[idx] = s;
    } else if (idx < ZD*OD + OD){
        int o = idx - ZD*OD;
        float s = 0.f;
        #pragma unroll
        for (int k=0;k<8;k++) s += g_dt[k*64+o];
        g_dc[o] = s;
    }
}

// out = H @ V^T + dconst ; 128 rows/block, thread = 4 rows x 8 cols; H16 -> fp32 smem
__global__ void __launch_bounds__(256) k_out(float* __restrict__ out){
    __shared__ float Vs[32*64];
    __shared__ float zs[128*33];
    int tid = threadIdx.x;
    int tc = tid & 7, tr = tid >> 3;
    int r0 = blockIdx.x * 128;
    int valid = NV - r0; if (valid > 128) valid = 128;

    ull acc[4][4];
    #pragma unroll
    for (int a=0;a<4;a++){
        #pragma unroll
        for (int b=0;b<4;b++) acc[a][b] = 0ULL;
    }

    for (int kk=0; kk<ZD; kk+=32){
        for (int t = tid; t < 512; t += 256)
            ((float4*)Vs)[t] = __ldg(((const float4*)(g_V + kk*64)) + t);
        for (int t = tid; t < 1024; t += 256){
            int r = t >> 3, c = t & 7;
            uint2 wv = (r < valid)
                ? __ldg(&g_H16[(size_t)(r0+r)*48 + (kk>>2) + c])
                : make_uint2(0u,0u);
            float2 a = __half22float2(*(__half2*)&wv.x);
            float2 b = __half22float2(*(__half2*)&wv.y);
            float* d = zs + r*33 + c*4;
            d[0]=a.x; d[1]=a.y; d[2]=b.x; d[3]=b.y;
        }
        __syncthreads();
        #pragma unroll 4
        for (int k=0;k<32;k++){
            ull vv[4];
            #pragma unroll
            for (int c=0;c<4;c++) vv[c] = ((const ull*)(Vs + k*64))[tc*4 + c];
            #pragma unroll
            for (int rr=0;rr<4;rr++){
                float z = zs[(tr*4+rr)*33 + k];
                ull zz = pack2(z, z);
                #pragma unroll
                for (int c=0;c<4;c++) fma2(acc[rr][c], zz, vv[c]);
            }
        }
        __syncthreads();
    }
    #pragma unroll
    for (int rr=0;rr<4;rr++){
        int row = r0 + tr*4 + rr;
        if (row < NV){
            float2* o2 = (float2*)(out + (size_t)row*64 + tc*8);
            #pragma unroll
            for (int c=0;c<4;c++){
                float2 p = unpack2(acc[rr][c]);
                p.x += g_dc[tc*8 + 2*c];
                p.y += g_dc[tc*8 + 2*c + 1];
                o2[c] = p;
            }
        }
    }
}

extern "C" void kernel_launch(void* const* d_in, const int* in_sizes, int n_in,
                              void* d_out, int out_size){
    const float* feats = (const float*)d_in[0];
    const int*   src   = (const int*)  d_in[1];
    const int*   dst   = (const int*)  d_in[2];
    const float* W0    = (const float*)d_in[3];
    const float* b0    = (const float*)d_in[4];
    const float* W1    = (const float*)d_in[5];
    const float* b1    = (const float*)d_in[6];
    const float* W2    = (const float*)d_in[7];
    const float* b2    = (const float*)d_in[8];
    const float* fcW   = (const float*)d_in[9];
    const float* fcb   = (const float*)d_in[10];
    const float* gamma = (const float*)d_in[11];
    const float* beta  = (const float*)d_in[12];
    const float* q     = (const float*)d_in[13];
    float* out = (float*)d_out;

    k_zero   <<<9375, 256>>>();                                   // #1
    k_deg    <<<6250, 256>>>(dst);                                // #2
    k_scan1  <<<98, 1024>>>();                                    // #3
    k_wgemm  <<<192, 256>>>(fcW, W0, W1, W2);                     // #4  <- profiled slot
    k_wbias  <<<64, 256>>>(fcW, b0, b1, b2, fcb);                 // #5
    k_scan3t0<<<391, 256>>>(feats);                               // #6
    k_place  <<<6250, 256>>>(src, dst);                           // #7
    k_hop    <<<12500, 256>>>(0, 0,  1);                          // #8
    k_hop    <<<12500, 256>>>(1, 16, 1);                          // #9
    k_hop    <<<12500, 256>>>(0, 32, 0);                          // #10
    k_gram   <<<148, 512>>>();                                    // #11
    k_stats  <<<512, 192>>>(gamma, beta, q);                      // #12
    k_vk     <<<49, 256>>>();                                     // #13
    k_out    <<<782, 256>>>(out);                                 // #14
}

// round 13
// speedup vs baseline: 2.7158x; 1.3793x over previous
#include <cuda_runtime.h>
#include <cuda_fp16.h>

#define NV 100000
#define NE 1600000
#define CSCP 2400000            // NE + 8*NV (padded CSC)
#define ZD 192
#define HD 512
#define OD 64
#define EPS 1e-5f

typedef unsigned long long ull;

__device__ __forceinline__ ull pack2(float lo, float hi){
    ull r; asm("mov.b64 %0, {%1,%2};" : "=l"(r) : "f"(lo), "f"(hi)); return r;
}
__device__ __forceinline__ void fma2(ull &d, ull a, ull b){
    asm("fma.rn.f32x2 %0, %1, %2, %0;" : "+l"(d) : "l"(a), "l"(b));
}
__device__ __forceinline__ float2 unpack2(ull v){
    float2 f; asm("mov.b64 {%0,%1}, %2;" : "=f"(f.x), "=f"(f.y) : "l"(v)); return f;
}
__device__ __forceinline__ unsigned smem_u32(const void* p){
    unsigned a;
    asm("{ .reg .u64 t; cvta.to.shared.u64 t, %1; cvt.u32.u64 %0, t; }" : "=r"(a) : "l"(p));
    return a;
}

// upper-triangle 16x16 tile list for S (12x12 tiles, i<=j): 78 tiles
__constant__ unsigned char c_i16[78] = {
    0,0,0,0,0,0,0,0,0,0,0,0,
    1,1,1,1,1,1,1,1,1,1,1,
    2,2,2,2,2,2,2,2,2,2,
    3,3,3,3,3,3,3,3,3,
    4,4,4,4,4,4,4,4,
    5,5,5,5,5,5,5,
    6,6,6,6,6,6,
    7,7,7,7,7,
    8,8,8,8,
    9,9,9,
    10,10,
    11};
__constant__ unsigned char c_j16[78] = {
    0,1,2,3,4,5,6,7,8,9,10,11,
    1,2,3,4,5,6,7,8,9,10,11,
    2,3,4,5,6,7,8,9,10,11,
    3,4,5,6,7,8,9,10,11,
    4,5,6,7,8,9,10,11,
    5,6,7,8,9,10,11,
    6,7,8,9,10,11,
    7,8,9,10,11,
    8,9,10,11,
    9,10,11,
    10,11,
    11};

// scratch (no allocations allowed)
__device__ int   g_deg[NV];
__device__ int   g_off[NV];
__device__ int   g_csc[CSCP];
__device__ float g_norm[NV];
__device__ uint2 g_tA16[(NV+1)*16];    // fp16 t, 64 halves/row; row NV = zeros (pad target)
__device__ uint2 g_tB16[(NV+1)*16];
__device__ uint2 g_H16[(size_t)NV*48]; // fp16 H: 192 halves/row
__device__ float g_S[ZD*ZD];           // Gram (upper triangle authoritative)
__device__ float g_cs[ZD];             // column sums
__device__ float g_M[HD*ZD];           // folded weights (atomically accumulated)
__device__ float g_cv[HD];             // folded bias
__device__ float g_av[HD];             // q*gamma*invstd
__device__ float g_dt[HD];             // per-channel const
__device__ float g_V[ZD*OD];
__device__ float g_dc[OD];
__device__ int   g_bsum[128];

// zero/init everything that is accumulated or pad-read; fill CSC with dummy index NV
__global__ void k_zero(){
    int i = blockIdx.x*256 + threadIdx.x;
    if (i < CSCP)  g_csc[i] = NV;
    if (i < NV)    g_deg[i] = 0;
    if (i < HD*ZD) g_M[i]   = 0.f;
    if (i < ZD*ZD) g_S[i]   = 0.f;
    if (i < ZD)    g_cs[i]  = 0.f;
    if (i < 16){
        g_tA16[NV*16 + i] = make_uint2(0u,0u);
        g_tB16[NV*16 + i] = make_uint2(0u,0u);
    }
}

// folded-weight GEMM: grid = 8 ko-tiles x 3 j x 8 K-chunks = 192 blocks
__global__ void __launch_bounds__(256) k_wgemm(const float* __restrict__ fcW,
                          const float* __restrict__ W0, const float* __restrict__ W1,
                          const float* __restrict__ W2){
    __shared__ float As[64][68];
    __shared__ float Bs[64][64];
    int b = blockIdx.x;
    int mt = b & 7;
    int j  = (b >> 3) % 3;
    int kc = b / 24;
    int ko0 = mt << 6, k0 = kc << 6;
    const float* W = (j==0)?W0:((j==1)?W1:W2);
    int tid = threadIdx.x;
    int ty = tid >> 4, tx = tid & 15;

    for (int t = tid; t < 1024; t += 256){
        int r = t >> 4, c4 = (t & 15) << 2;
        float4 v = __ldg((const float4*)(fcW + (size_t)(ko0 + r)*1536 + j*512 + k0 + c4));
        As[r][c4] = v.x; As[r][c4+1] = v.y; As[r][c4+2] = v.z; As[r][c4+3] = v.w;
    }
    for (int t = tid; t < 1024; t += 256){
        int r = t >> 4, c4 = (t & 15) << 2;
        float4 v = __ldg((const float4*)(W + (size_t)(k0 + r)*64 + c4));
        *(float4*)&Bs[r][c4] = v;
    }
    __syncthreads();

    float acc[4][4] = {};
    #pragma unroll 8
    for (int k = 0; k < 64; k++){
        float a0 = As[ty*4+0][k];
        float a1 = As[ty*4+1][k];
        float a2 = As[ty*4+2][k];
        float a3 = As[ty*4+3][k];
        float4 bv = *(const float4*)&Bs[k][tx*4];
        acc[0][0]=fmaf(a0,bv.x,acc[0][0]); acc[0][1]=fmaf(a0,bv.y,acc[0][1]);
        acc[0][2]=fmaf(a0,bv.z,acc[0][2]); acc[0][3]=fmaf(a0,bv.w,acc[0][3]);
        acc[1][0]=fmaf(a1,bv.x,acc[1][0]); acc[1][1]=fmaf(a1,bv.y,acc[1][1]);
        acc[1][2]=fmaf(a1,bv.z,acc[1][2]); acc[1][3]=fmaf(a1,bv.w,acc[1][3]);
        acc[2][0]=fmaf(a2,bv.x,acc[2][0]); acc[2][1]=fmaf(a2,bv.y,acc[2][1]);
        acc[2][2]=fmaf(a2,bv.z,acc[2][2]); acc[2][3]=fmaf(a2,bv.w,acc[2][3]);
        acc[3][0]=fmaf(a3,bv.x,acc[3][0]); acc[3][1]=fmaf(a3,bv.y,acc[3][1]);
        acc[3][2]=fmaf(a3,bv.z,acc[3][2]); acc[3][3]=fmaf(a3,bv.w,acc[3][3]);
    }
    #pragma unroll
    for (int r = 0; r < 4; r++){
        int ko = ko0 + ty*4 + r;
        #pragma unroll
        for (int c = 0; c < 4; c++)
            atomicAdd(&g_M[(size_t)ko*ZD + j*64 + tx*4 + c], acc[r][c]);
    }
}

// bias fold: warp per channel
__global__ void k_wbias(const float* __restrict__ fcW,
                        const float* __restrict__ b0, const float* __restrict__ b1,
                        const float* __restrict__ b2, const float* __restrict__ fcb){
    int w = (blockIdx.x*256 + threadIdx.x) >> 5;
    int lane = threadIdx.x & 31;
    if (w >= HD) return;
    const float* fr = fcW + (size_t)w*1536;
    float s = 0.f;
    #pragma unroll 4
    for (int h = lane; h < HD; h += 32)
        s += fr[h]*b0[h] + fr[512+h]*b1[h] + fr[1024+h]*b2[h];
    #pragma unroll
    for (int o=16;o;o>>=1) s += __shfl_xor_sync(0xffffffffu, s, o);
    if (lane == 0) g_cv[w] = s + fcb[w];
}

__global__ void k_deg(const int* __restrict__ dst){
    int e = blockIdx.x*256 + threadIdx.x;
    if (e < NE) atomicAdd(&g_deg[dst[e]], 1);
}

// scan of PADDED degrees ((d+7)&~7) -> 8-aligned slot starts
__global__ void k_scan1(){
    __shared__ int sh[1024];
    int t = threadIdx.x, i = blockIdx.x*1024 + t;
    int d = (i < NV) ? g_deg[i] : 0;
    int v = (d + 7) & ~7;
    sh[t] = v; __syncthreads();
    for (int off=1; off<1024; off<<=1){
        int x = (t >= off) ? sh[t-off] : 0; __syncthreads();
        sh[t] += x; __syncthreads();
    }
    if (i < NV) g_off[i] = sh[t] - v;
    if (t == 1023) g_bsum[blockIdx.x] = sh[1023];
}

// finalize slot starts/norm AND scale feats -> tA16 (fp16); inline block-sum prefix
__global__ void k_scan3t0(const float* __restrict__ feats){
    __shared__ float snorm[256];
    __shared__ int sboff;
    int t = threadIdx.x;
    int i = blockIdx.x*256 + t;
    int chunk = blockIdx.x >> 2;
    if (t < 32){
        int s = 0;
        for (int j = t; j < chunk; j += 32) s += g_bsum[j];
        #pragma unroll
        for (int o=16;o;o>>=1) s += __shfl_xor_sync(0xffffffffu, s, o);
        if (t == 0) sboff = s;
    }
    __syncthreads();
    if (i < NV){
        g_off[i] += sboff;
        int d = g_deg[i];
        float nv = rsqrtf((float)(d > 1 ? d : 1));
        g_norm[i] = nv;
        snorm[t]  = nv;
    }
    __syncthreads();
    int base4 = blockIdx.x*256*16;
    for (int tt = t; tt < 256*16; tt += 256){
        int r = tt >> 4;
        if (blockIdx.x*256 + r < NV){
            float4 v = __ldg(((const float4*)feats) + base4 + tt);
            float nv = snorm[r];
            uint2 o;
            *(__half2*)&o.x = __floats2half2_rn(v.x*nv, v.y*nv);
            *(__half2*)&o.y = __floats2half2_rn(v.z*nv, v.w*nv);
            g_tA16[base4 + tt] = o;
        }
    }
}

// place edges; cursor is g_off itself
__global__ void k_place(const int* __restrict__ src, const int* __restrict__ dst){
    int e = blockIdx.x*256 + threadIdx.x;
    if (e < NE){
        int p = atomicAdd(&g_off[dst[e]], 1);
        g_csc[p] = src[e];
    }
}

// hop: warp per node; uniform ceil(deg/8) iters
__global__ void k_hop(int sel, int coff16, int wt){
    int gw   = (blockIdx.x*blockDim.x + threadIdx.x) >> 5;
    int lane = threadIdx.x & 31;
    if (gw >= NV) return;
    const uint2* tin  = sel ? g_tB16 : g_tA16;
    uint2*       tout = sel ? g_tA16 : g_tB16;
    int dv = g_deg[gw];
    int s  = g_off[gw] - dv;
    int niter = (dv + 7) >> 3;
    int half = lane >> 4;
    int c4   = lane & 15;
    float ax=0.f, ay=0.f, az=0.f, aw=0.f;
    const int* base = g_csc + s + half*4;
    for (int it = 0; it < niter; it++){
        int4 u = *(const int4*)(base + it*8);
        uint2 w0 = __ldg(&tin[u.x*16 + c4]);
        uint2 w1 = __ldg(&tin[u.y*16 + c4]);
        uint2 w2 = __ldg(&tin[u.z*16 + c4]);
        uint2 w3 = __ldg(&tin[u.w*16 + c4]);
        float2 a0 = __half22float2(*(__half2*)&w0.x), b0 = __half22float2(*(__half2*)&w0.y);
        float2 a1 = __half22float2(*(__half2*)&w1.x), b1 = __half22float2(*(__half2*)&w1.y);
        float2 a2 = __half22float2(*(__half2*)&w2.x), b2 = __half22float2(*(__half2*)&w2.y);
        float2 a3 = __half22float2(*(__half2*)&w3.x), b3 = __half22float2(*(__half2*)&w3.y);
        ax += (a0.x + a1.x) + (a2.x + a3.x);
        ay += (a0.y + a1.y) + (a2.y + a3.y);
        az += (b0.x + b1.x) + (b2.x + b3.x);
        aw += (b0.y + b1.y) + (b2.y + b3.y);
    }
    ax += __shfl_xor_sync(0xffffffffu, ax, 16);
    ay += __shfl_xor_sync(0xffffffffu, ay, 16);
    az += __shfl_xor_sync(0xffffffffu, az, 16);
    aw += __shfl_xor_sync(0xffffffffu, aw, 16);
    if (half == 0){
        float nv = g_norm[gw];
        float hx = ax*nv, hy = ay*nv, hz = az*nv, hw = aw*nv;
        uint2 hh;
        *(__half2*)&hh.x = __floats2half2_rn(hx, hy);
        *(__half2*)&hh.y = __floats2half2_rn(hz, hw);
        g_H16[(size_t)gw*48 + coff16 + c4] = hh;
        if (wt){
            uint2 o;
            *(__half2*)&o.x = __floats2half2_rn(hx*nv, hy*nv);
            *(__half2*)&o.y = __floats2half2_rn(hz*nv, hw*nv);
            tout[gw*16 + c4] = o;
        }
    }
}

// HMMA Gram: S = Z^T Z via mma.m16n8k16; 78 upper tiles, 16 warps x <=5 tiles
// smem chunk: 64 nodes x 200 halves (pad 8) -> conflict-free ldmatrix, 16B-aligned
__global__ void __launch_bounds__(512,1) k_gram(){
    __shared__ __align__(16) __half zs16[64*200];
    int tid = threadIdx.x;
    int w = tid >> 5, lane = tid & 31;
    int nt = (w < 14) ? 5 : 4;                 // 78 = 14*5 + 2*4
    int ti[5], tj[5];
    #pragma unroll
    for (int k=0;k<5;k++){
        int t = w + (k<<4);
        if (t < 78){ ti[k] = ((int)c_i16[t])<<4; tj[k] = ((int)c_j16[t])<<4; }
        else       { ti[k] = 0;                 tj[k] = 0; }
    }
    float d[5][8];
    #pragma unroll
    for (int k=0;k<5;k++){
        #pragma unroll
        for (int m=0;m<8;m++) d[k][m] = 0.f;
    }
    float csacc = 0.f;
    unsigned zbase = smem_u32(zs16);
    int r8  = lane & 7;
    int mat = lane >> 3;
    // A quadrants: {k, k+8} x {col, col+8}; a-frag order: (m0-7,k0-7),(m8-15,k0-7),(m0-7,k8-15),(m8-15,k8-15)
    int aK = r8 + ((mat & 2) ? 8 : 0);
    int aC = (mat & 1) ? 8 : 0;
    // B quadrants for {b0_n0,b1_n0,b0_n8,b1_n8}
    int bK = r8 + ((mat & 1) ? 8 : 0);
    int bC = (mat & 2) ? 8 : 0;

    int ntile = (NV + 63) >> 6;
    for (int tile = blockIdx.x; tile < ntile; tile += gridDim.x){
        int r0 = tile << 6;
        int valid = NV - r0; if (valid > 64) valid = 64;
        for (int t = tid; t < 64*48; t += 512){
            int r = t / 48, c = t - r*48;
            uint2 wv = (r < valid) ? __ldg(&g_H16[(size_t)(r0+r)*48 + c])
                                   : make_uint2(0u,0u);
            *(uint2*)&zs16[r*200 + c*4] = wv;
        }
        __syncthreads();
        #pragma unroll
        for (int ks = 0; ks < 4; ks++){
            int k0 = ks << 4;
            #pragma unroll
            for (int k=0;k<5;k++){
                if (k >= nt) break;
                unsigned aaddr = zbase + (unsigned)(((k0 + aK)*200 + ti[k] + aC) << 1);
                unsigned baddr = zbase + (unsigned)(((k0 + bK)*200 + tj[k] + bC) << 1);
                unsigned a0,a1,a2,a3,b0,b1,b2,b3;
                asm volatile("ldmatrix.sync.aligned.m8n8.x4.trans.shared.b16 {%0,%1,%2,%3}, [%4];"
                    : "=r"(a0),"=r"(a1),"=r"(a2),"=r"(a3) : "r"(aaddr));
                asm volatile("ldmatrix.sync.aligned.m8n8.x4.trans.shared.b16 {%0,%1,%2,%3}, [%4];"
                    : "=r"(b0),"=r"(b1),"=r"(b2),"=r"(b3) : "r"(baddr));
                asm volatile("mma.sync.aligned.m16n8k16.row.col.f32.f16.f16.f32 "
                    "{%0,%1,%2,%3}, {%4,%5,%6,%7}, {%8,%9}, {%0,%1,%2,%3};"
                    : "+f"(d[k][0]),"+f"(d[k][1]),"+f"(d[k][2]),"+f"(d[k][3])
                    : "r"(a0),"r"(a1),"r"(a2),"r"(a3), "r"(b0),"r"(b1));
                asm volatile("mma.sync.aligned.m16n8k16.row.col.f32.f16.f16.f32 "
                    "{%0,%1,%2,%3}, {%4,%5,%6,%7}, {%8,%9}, {%0,%1,%2,%3};"
                    : "+f"(d[k][4]),"+f"(d[k][5]),"+f"(d[k][6]),"+f"(d[k][7])
                    : "r"(a0),"r"(a1),"r"(a2),"r"(a3), "r"(b2),"r"(b3));
            }
        }
        if (tid < ZD){
            float s = 0.f;
            #pragma unroll 8
            for (int r=0; r<64; r++) s += __half2float(zs16[r*200 + tid]);
            csacc += s;
        }
        __syncthreads();
    }
    int g = lane >> 2, tq = lane & 3;
    #pragma unroll
    for (int k=0;k<5;k++){
        if (k >= nt) break;
        int i0 = ti[k], j0 = tj[k];
        atomicAdd(&g_S[(i0+g  )*ZD + j0   + 2*tq    ], d[k][0]);
        atomicAdd(&g_S[(i0+g  )*ZD + j0   + 2*tq + 1], d[k][1]);
        atomicAdd(&g_S[(i0+g+8)*ZD + j0   + 2*tq    ], d[k][2]);
        atomicAdd(&g_S[(i0+g+8)*ZD + j0   + 2*tq + 1], d[k][3]);
        atomicAdd(&g_S[(i0+g  )*ZD + j0+8 + 2*tq    ], d[k][4]);
        atomicAdd(&g_S[(i0+g  )*ZD + j0+8 + 2*tq + 1], d[k][5]);
        atomicAdd(&g_S[(i0+g+8)*ZD + j0+8 + 2*tq    ], d[k][6]);
        atomicAdd(&g_S[(i0+g+8)*ZD + j0+8 + 2*tq + 1], d[k][7]);
    }
    if (tid < ZD) atomicAdd(&g_cs[tid], csacc);
}

// BN stats per output channel (reads upper triangle of S); fold with q
__global__ void k_stats(const float* __restrict__ gamma, const float* __restrict__ beta,
                        const float* __restrict__ q){
    __shared__ float m[ZD], r1[ZD], r2[ZD];
    int ko = blockIdx.x, t = threadIdx.x;
    m[t] = g_M[ko*ZD + t];
    __syncthreads();
    float w = 0.f;
    #pragma unroll 4
    for (int j=0;j<ZD;j++){
        float sv = (j >= t) ? g_S[t*ZD + j] : g_S[j*ZD + t];
        w = fmaf(sv, m[j], w);
    }
    r1[t] = m[t]*w;
    r2[t] = m[t]*g_cs[t];
    __syncthreads();
    for (int s=96; s>=3; s>>=1){
        if (t < s){ r1[t] += r1[t+s]; r2[t] += r2[t+s]; }
        __syncthreads();
    }
    if (t == 0){
        float qf  = r1[0]+r1[1]+r1[2];
        float mz  = (r2[0]+r2[1]+r2[2]) * (1.0f/NV);
        float var = qf*(1.0f/NV) - mz*mz;
        float c   = g_cv[ko];
        float inv = rsqrtf(var + EPS);
        float sc  = gamma[ko]*inv;
        float tsh = beta[ko] - (mz + c)*sc;
        float qk  = q[ko >> 6];
        g_av[ko] = qk*sc;
        g_dt[ko] = qk*(sc*c + tsh);
    }
}

__global__ void k_vk(){
    int idx = blockIdx.x*256 + threadIdx.x;
    if (idx < ZD*OD){
        int i = idx >> 6, o = idx & 63;
        float s = 0.f;
        #pragma unroll
        for (int k=0;k<8;k++){ int ko = k*64+o; s = fmaf(g_av[ko], g_M[ko*ZD + i], s); }
        g_V[idx] = s;
    } else if (idx < ZD*OD + OD){
        int o = idx - ZD*OD;
        float s = 0.f;
        #pragma unroll
        for (int k=0;k<8;k++) s += g_dt[k*64+o];
        g_dc[o] = s;
    }
}

// out = H @ V^T + dconst ; 128 rows/block, thread = 4 rows x 8 cols; H16 -> fp32 smem
__global__ void __launch_bounds__(256) k_out(float* __restrict__ out){
    __shared__ float Vs[32*64];
    __shared__ float zs[128*33];
    int tid = threadIdx.x;
    int tc = tid & 7, tr = tid >> 3;
    int r0 = blockIdx.x * 128;
    int valid = NV - r0; if (valid > 128) valid = 128;

    ull acc[4][4];
    #pragma unroll
    for (int a=0;a<4;a++){
        #pragma unroll
        for (int b=0;b<4;b++) acc[a][b] = 0ULL;
    }

    for (int kk=0; kk<ZD; kk+=32){
        for (int t = tid; t < 512; t += 256)
            ((float4*)Vs)[t] = __ldg(((const float4*)(g_V + kk*64)) + t);
        for (int t = tid; t < 1024; t += 256){
            int r = t >> 3, c = t & 7;
            uint2 wv = (r < valid)
                ? __ldg(&g_H16[(size_t)(r0+r)*48 + (kk>>2) + c])
                : make_uint2(0u,0u);
            float2 a = __half22float2(*(__half2*)&wv.x);
            float2 b = __half22float2(*(__half2*)&wv.y);
            float* d = zs + r*33 + c*4;
            d[0]=a.x; d[1]=a.y; d[2]=b.x; d[3]=b.y;
        }
        __syncthreads();
        #pragma unroll 4
        for (int k=0;k<32;k++){
            ull vv[4];
            #pragma unroll
            for (int c=0;c<4;c++) vv[c] = ((const ull*)(Vs + k*64))[tc*4 + c];
            #pragma unroll
            for (int rr=0;rr<4;rr++){
                float z = zs[(tr*4+rr)*33 + k];
                ull zz = pack2(z, z);
                #pragma unroll
                for (int c=0;c<4;c++) fma2(acc[rr][c], zz, vv[c]);
            }
        }
        __syncthreads();
    }
    #pragma unroll
    for (int rr=0;rr<4;rr++){
        int row = r0 + tr*4 + rr;
        if (row < NV){
            float2* o2 = (float2*)(out + (size_t)row*64 + tc*8);
            #pragma unroll
            for (int c=0;c<4;c++){
                float2 p = unpack2(acc[rr][c]);
                p.x += g_dc[tc*8 + 2*c];
                p.y += g_dc[tc*8 + 2*c + 1];
                o2[c] = p;
            }
        }
    }
}

extern "C" void kernel_launch(void* const* d_in, const int* in_sizes, int n_in,
                              void* d_out, int out_size){
    const float* feats = (const float*)d_in[0];
    const int*   src   = (const int*)  d_in[1];
    const int*   dst   = (const int*)  d_in[2];
    const float* W0    = (const float*)d_in[3];
    const float* b0    = (const float*)d_in[4];
    const float* W1    = (const float*)d_in[5];
    const float* b1    = (const float*)d_in[6];
    const float* W2    = (const float*)d_in[7];
    const float* b2    = (const float*)d_in[8];
    const float* fcW   = (const float*)d_in[9];
    const float* fcb   = (const float*)d_in[10];
    const float* gamma = (const float*)d_in[11];
    const float* beta  = (const float*)d_in[12];
    const float* q     = (const float*)d_in[13];
    float* out = (float*)d_out;

    k_zero   <<<9375, 256>>>();                                   // #1
    k_deg    <<<6250, 256>>>(dst);                                // #2
    k_scan1  <<<98, 1024>>>();                                    // #3
    k_wgemm  <<<192, 256>>>(fcW, W0, W1, W2);                     // #4
    k_wbias  <<<64, 256>>>(fcW, b0, b1, b2, fcb);                 // #5
    k_scan3t0<<<391, 256>>>(feats);                               // #6
    k_place  <<<6250, 256>>>(src, dst);                           // #7
    k_hop    <<<12500, 256>>>(0, 0,  1);                          // #8
    k_hop    <<<12500, 256>>>(1, 16, 1);                          // #9
    k_hop    <<<12500, 256>>>(0, 32, 0);                          // #10
    k_gram   <<<148, 512>>>();                                    // #11
    k_stats  <<<512, 192>>>(gamma, beta, q);                      // #12
    k_vk     <<<49, 256>>>();                                     // #13
    k_out    <<<782, 256>>>(out);                                 // #14
}

// round 15
// speedup vs baseline: 3.4296x; 1.2628x over previous
#include <cuda_runtime.h>
#include <cuda_fp16.h>

#define NV 100000
#define NE 1600000
#define CSCP 2400000            // NE + 8*NV (padded CSC)
#define ZD 192
#define HD 512
#define OD 64
#define EPS 1e-5f

typedef unsigned long long ull;

__device__ __forceinline__ unsigned smem_u32(const void* p){
    unsigned a;
    asm("{ .reg .u64 t; cvta.to.shared.u64 t, %1; cvt.u32.u64 %0, t; }" : "=r"(a) : "l"(p));
    return a;
}

// upper-triangle 16x16 tile list for S (12x12 tiles, i<=j): 78 tiles
__constant__ unsigned char c_i16[78] = {
    0,0,0,0,0,0,0,0,0,0,0,0,
    1,1,1,1,1,1,1,1,1,1,1,
    2,2,2,2,2,2,2,2,2,2,
    3,3,3,3,3,3,3,3,3,
    4,4,4,4,4,4,4,4,
    5,5,5,5,5,5,5,
    6,6,6,6,6,6,
    7,7,7,7,7,
    8,8,8,8,
    9,9,9,
    10,10,
    11};
__constant__ unsigned char c_j16[78] = {
    0,1,2,3,4,5,6,7,8,9,10,11,
    1,2,3,4,5,6,7,8,9,10,11,
    2,3,4,5,6,7,8,9,10,11,
    3,4,5,6,7,8,9,10,11,
    4,5,6,7,8,9,10,11,
    5,6,7,8,9,10,11,
    6,7,8,9,10,11,
    7,8,9,10,11,
    8,9,10,11,
    9,10,11,
    10,11,
    11};

// scratch (no allocations allowed)
__device__ int   g_deg[NV];
__device__ int   g_off[NV];
__device__ int   g_csc[CSCP];
__device__ float g_norm[NV];
__device__ uint2 g_tA16[(NV+1)*16];    // fp16 t, 64 halves/row; row NV = zeros (pad target)
__device__ uint2 g_tB16[(NV+1)*16];
__device__ uint2 g_H16[(size_t)NV*48]; // fp16 H: 192 halves/row
__device__ float g_S[ZD*ZD];           // Gram (upper triangle authoritative)
__device__ float g_cs[ZD];             // column sums
__device__ float g_M[HD*ZD];           // folded weights (atomically accumulated)
__device__ float g_cv[HD];             // folded bias
__device__ float g_av[HD];             // q*gamma*invstd
__device__ float g_dt[HD];             // per-channel const
__device__ __half g_V16[ZD*OD];        // fused matrix, fp16
__device__ float g_dc[OD];
__device__ int   g_bsum[128];

// zero/init everything that is accumulated or pad-read; fill CSC with dummy index NV
__global__ void k_zero(){
    int i = blockIdx.x*256 + threadIdx.x;
    if (i < CSCP)  g_csc[i] = NV;
    if (i < NV)    g_deg[i] = 0;
    if (i < HD*ZD) g_M[i]   = 0.f;
    if (i < ZD*ZD) g_S[i]   = 0.f;
    if (i < ZD)    g_cs[i]  = 0.f;
    if (i < 16){
        g_tA16[NV*16 + i] = make_uint2(0u,0u);
        g_tB16[NV*16 + i] = make_uint2(0u,0u);
    }
}

// folded-weight GEMM: grid = 8 ko-tiles x 3 j x 8 K-chunks = 192 blocks
__global__ void __launch_bounds__(256) k_wgemm(const float* __restrict__ fcW,
                          const float* __restrict__ W0, const float* __restrict__ W1,
                          const float* __restrict__ W2){
    __shared__ float As[64][68];
    __shared__ float Bs[64][64];
    int b = blockIdx.x;
    int mt = b & 7;
    int j  = (b >> 3) % 3;
    int kc = b / 24;
    int ko0 = mt << 6, k0 = kc << 6;
    const float* W = (j==0)?W0:((j==1)?W1:W2);
    int tid = threadIdx.x;
    int ty = tid >> 4, tx = tid & 15;

    for (int t = tid; t < 1024; t += 256){
        int r = t >> 4, c4 = (t & 15) << 2;
        float4 v = __ldg((const float4*)(fcW + (size_t)(ko0 + r)*1536 + j*512 + k0 + c4));
        As[r][c4] = v.x; As[r][c4+1] = v.y; As[r][c4+2] = v.z; As[r][c4+3] = v.w;
    }
    for (int t = tid; t < 1024; t += 256){
        int r = t >> 4, c4 = (t & 15) << 2;
        float4 v = __ldg((const float4*)(W + (size_t)(k0 + r)*64 + c4));
        *(float4*)&Bs[r][c4] = v;
    }
    __syncthreads();

    float acc[4][4] = {};
    #pragma unroll 8
    for (int k = 0; k < 64; k++){
        float a0 = As[ty*4+0][k];
        float a1 = As[ty*4+1][k];
        float a2 = As[ty*4+2][k];
        float a3 = As[ty*4+3][k];
        float4 bv = *(const float4*)&Bs[k][tx*4];
        acc[0][0]=fmaf(a0,bv.x,acc[0][0]); acc[0][1]=fmaf(a0,bv.y,acc[0][1]);
        acc[0][2]=fmaf(a0,bv.z,acc[0][2]); acc[0][3]=fmaf(a0,bv.w,acc[0][3]);
        acc[1][0]=fmaf(a1,bv.x,acc[1][0]); acc[1][1]=fmaf(a1,bv.y,acc[1][1]);
        acc[1][2]=fmaf(a1,bv.z,acc[1][2]); acc[1][3]=fmaf(a1,bv.w,acc[1][3]);
        acc[2][0]=fmaf(a2,bv.x,acc[2][0]); acc[2][1]=fmaf(a2,bv.y,acc[2][1]);
        acc[2][2]=fmaf(a2,bv.z,acc[2][2]); acc[2][3]=fmaf(a2,bv.w,acc[2][3]);
        acc[3][0]=fmaf(a3,bv.x,acc[3][0]); acc[3][1]=fmaf(a3,bv.y,acc[3][1]);
        acc[3][2]=fmaf(a3,bv.z,acc[3][2]); acc[3][3]=fmaf(a3,bv.w,acc[3][3]);
    }
    #pragma unroll
    for (int r = 0; r < 4; r++){
        int ko = ko0 + ty*4 + r;
        #pragma unroll
        for (int c = 0; c < 4; c++)
            atomicAdd(&g_M[(size_t)ko*ZD + j*64 + tx*4 + c], acc[r][c]);
    }
}

// bias fold: warp per channel
__global__ void k_wbias(const float* __restrict__ fcW,
                        const float* __restrict__ b0, const float* __restrict__ b1,
                        const float* __restrict__ b2, const float* __restrict__ fcb){
    int w = (blockIdx.x*256 + threadIdx.x) >> 5;
    int lane = threadIdx.x & 31;
    if (w >= HD) return;
    const float* fr = fcW + (size_t)w*1536;
    float s = 0.f;
    #pragma unroll 4
    for (int h = lane; h < HD; h += 32)
        s += fr[h]*b0[h] + fr[512+h]*b1[h] + fr[1024+h]*b2[h];
    #pragma unroll
    for (int o=16;o;o>>=1) s += __shfl_xor_sync(0xffffffffu, s, o);
    if (lane == 0) g_cv[w] = s + fcb[w];
}

__global__ void k_deg(const int* __restrict__ dst){
    int e = blockIdx.x*256 + threadIdx.x;
    if (e < NE) atomicAdd(&g_deg[dst[e]], 1);
}

// scan of PADDED degrees ((d+7)&~7) -> 8-aligned slot starts
__global__ void k_scan1(){
    __shared__ int sh[1024];
    int t = threadIdx.x, i = blockIdx.x*1024 + t;
    int d = (i < NV) ? g_deg[i] : 0;
    int v = (d + 7) & ~7;
    sh[t] = v; __syncthreads();
    for (int off=1; off<1024; off<<=1){
        int x = (t >= off) ? sh[t-off] : 0; __syncthreads();
        sh[t] += x; __syncthreads();
    }
    if (i < NV) g_off[i] = sh[t] - v;
    if (t == 1023) g_bsum[blockIdx.x] = sh[1023];
}

// finalize slot starts/norm AND scale feats -> tA16 (fp16); inline block-sum prefix
__global__ void k_scan3t0(const float* __restrict__ feats){
    __shared__ float snorm[256];
    __shared__ int sboff;
    int t = threadIdx.x;
    int i = blockIdx.x*256 + t;
    int chunk = blockIdx.x >> 2;
    if (t < 32){
        int s = 0;
        for (int j = t; j < chunk; j += 32) s += g_bsum[j];
        #pragma unroll
        for (int o=16;o;o>>=1) s += __shfl_xor_sync(0xffffffffu, s, o);
        if (t == 0) sboff = s;
    }
    __syncthreads();
    if (i < NV){
        g_off[i] += sboff;
        int d = g_deg[i];
        float nv = rsqrtf((float)(d > 1 ? d : 1));
        g_norm[i] = nv;
        snorm[t]  = nv;
    }
    __syncthreads();
    int base4 = blockIdx.x*256*16;
    for (int tt = t; tt < 256*16; tt += 256){
        int r = tt >> 4;
        if (blockIdx.x*256 + r < NV){
            float4 v = __ldg(((const float4*)feats) + base4 + tt);
            float nv = snorm[r];
            uint2 o;
            *(__half2*)&o.x = __floats2half2_rn(v.x*nv, v.y*nv);
            *(__half2*)&o.y = __floats2half2_rn(v.z*nv, v.w*nv);
            g_tA16[base4 + tt] = o;
        }
    }
}

// place edges; cursor is g_off itself
__global__ void k_place(const int* __restrict__ src, const int* __restrict__ dst){
    int e = blockIdx.x*256 + threadIdx.x;
    if (e < NE){
        int p = atomicAdd(&g_off[dst[e]], 1);
        g_csc[p] = src[e];
    }
}

// hop: warp per node; uniform ceil(deg/8) iters
__global__ void k_hop(int sel, int coff16, int wt){
    int gw   = (blockIdx.x*blockDim.x + threadIdx.x) >> 5;
    int lane = threadIdx.x & 31;
    if (gw >= NV) return;
    const uint2* tin  = sel ? g_tB16 : g_tA16;
    uint2*       tout = sel ? g_tA16 : g_tB16;
    int dv = g_deg[gw];
    int s  = g_off[gw] - dv;
    int niter = (dv + 7) >> 3;
    int half = lane >> 4;
    int c4   = lane & 15;
    float ax=0.f, ay=0.f, az=0.f, aw=0.f;
    const int* base = g_csc + s + half*4;
    for (int it = 0; it < niter; it++){
        int4 u = *(const int4*)(base + it*8);
        uint2 w0 = __ldg(&tin[u.x*16 + c4]);
        uint2 w1 = __ldg(&tin[u.y*16 + c4]);
        uint2 w2 = __ldg(&tin[u.z*16 + c4]);
        uint2 w3 = __ldg(&tin[u.w*16 + c4]);
        float2 a0 = __half22float2(*(__half2*)&w0.x), b0 = __half22float2(*(__half2*)&w0.y);
        float2 a1 = __half22float2(*(__half2*)&w1.x), b1 = __half22float2(*(__half2*)&w1.y);
        float2 a2 = __half22float2(*(__half2*)&w2.x), b2 = __half22float2(*(__half2*)&w2.y);
        float2 a3 = __half22float2(*(__half2*)&w3.x), b3 = __half22float2(*(__half2*)&w3.y);
        ax += (a0.x + a1.x) + (a2.x + a3.x);
        ay += (a0.y + a1.y) + (a2.y + a3.y);
        az += (b0.x + b1.x) + (b2.x + b3.x);
        aw += (b0.y + b1.y) + (b2.y + b3.y);
    }
    ax += __shfl_xor_sync(0xffffffffu, ax, 16);
    ay += __shfl_xor_sync(0xffffffffu, ay, 16);
    az += __shfl_xor_sync(0xffffffffu, az, 16);
    aw += __shfl_xor_sync(0xffffffffu, aw, 16);
    if (half == 0){
        float nv = g_norm[gw];
        float hx = ax*nv, hy = ay*nv, hz = az*nv, hw = aw*nv;
        uint2 hh;
        *(__half2*)&hh.x = __floats2half2_rn(hx, hy);
        *(__half2*)&hh.y = __floats2half2_rn(hz, hw);
        g_H16[(size_t)gw*48 + coff16 + c4] = hh;
        if (wt){
            uint2 o;
            *(__half2*)&o.x = __floats2half2_rn(hx*nv, hy*nv);
            *(__half2*)&o.y = __floats2half2_rn(hz*nv, hw*nv);
            tout[gw*16 + c4] = o;
        }
    }
}

// HMMA Gram: S = Z^T Z via mma.m16n8k16; 78 upper tiles, 16 warps x <=5 tiles
__global__ void __launch_bounds__(512,1) k_gram(){
    __shared__ __align__(16) __half zs16[64*200];
    int tid = threadIdx.x;
    int w = tid >> 5, lane = tid & 31;
    int nt = (w < 14) ? 5 : 4;                 // 78 = 14*5 + 2*4
    int ti[5], tj[5];
    #pragma unroll
    for (int k=0;k<5;k++){
        int t = w + (k<<4);
        if (t < 78){ ti[k] = ((int)c_i16[t])<<4; tj[k] = ((int)c_j16[t])<<4; }
        else       { ti[k] = 0;                 tj[k] = 0; }
    }
    float d[5][8];
    #pragma unroll
    for (int k=0;k<5;k++){
        #pragma unroll
        for (int m=0;m<8;m++) d[k][m] = 0.f;
    }
    float csacc = 0.f;
    unsigned zbase = smem_u32(zs16);
    int r8  = lane & 7;
    int mat = lane >> 3;
    int aK = r8 + ((mat & 2) ? 8 : 0);
    int aC = (mat & 1) ? 8 : 0;
    int bK = r8 + ((mat & 1) ? 8 : 0);
    int bC = (mat & 2) ? 8 : 0;

    int ntile = (NV + 63) >> 6;
    for (int tile = blockIdx.x; tile < ntile; tile += gridDim.x){
        int r0 = tile << 6;
        int valid = NV - r0; if (valid > 64) valid = 64;
        for (int t = tid; t < 64*48; t += 512){
            int r = t / 48, c = t - r*48;
            uint2 wv = (r < valid) ? __ldg(&g_H16[(size_t)(r0+r)*48 + c])
                                   : make_uint2(0u,0u);
            *(uint2*)&zs16[r*200 + c*4] = wv;
        }
        __syncthreads();
        #pragma unroll
        for (int ks = 0; ks < 4; ks++){
            int k0 = ks << 4;
            #pragma unroll
            for (int k=0;k<5;k++){
                if (k >= nt) break;
                unsigned aaddr = zbase + (unsigned)(((k0 + aK)*200 + ti[k] + aC) << 1);
                unsigned baddr = zbase + (unsigned)(((k0 + bK)*200 + tj[k] + bC) << 1);
                unsigned a0,a1,a2,a3,b0,b1,b2,b3;
                asm volatile("ldmatrix.sync.aligned.m8n8.x4.trans.shared.b16 {%0,%1,%2,%3}, [%4];"
                    : "=r"(a0),"=r"(a1),"=r"(a2),"=r"(a3) : "r"(aaddr));
                asm volatile("ldmatrix.sync.aligned.m8n8.x4.trans.shared.b16 {%0,%1,%2,%3}, [%4];"
                    : "=r"(b0),"=r"(b1),"=r"(b2),"=r"(b3) : "r"(baddr));
                asm volatile("mma.sync.aligned.m16n8k16.row.col.f32.f16.f16.f32 "
                    "{%0,%1,%2,%3}, {%4,%5,%6,%7}, {%8,%9}, {%0,%1,%2,%3};"
                    : "+f"(d[k][0]),"+f"(d[k][1]),"+f"(d[k][2]),"+f"(d[k][3])
                    : "r"(a0),"r"(a1),"r"(a2),"r"(a3), "r"(b0),"r"(b1));
                asm volatile("mma.sync.aligned.m16n8k16.row.col.f32.f16.f16.f32 "
                    "{%0,%1,%2,%3}, {%4,%5,%6,%7}, {%8,%9}, {%0,%1,%2,%3};"
                    : "+f"(d[k][4]),"+f"(d[k][5]),"+f"(d[k][6]),"+f"(d[k][7])
                    : "r"(a0),"r"(a1),"r"(a2),"r"(a3), "r"(b2),"r"(b3));
            }
        }
        if (tid < ZD){
            float s = 0.f;
            #pragma unroll 8
            for (int r=0; r<64; r++) s += __half2float(zs16[r*200 + tid]);
            csacc += s;
        }
        __syncthreads();
    }
    int g = lane >> 2, tq = lane & 3;
    #pragma unroll
    for (int k=0;k<5;k++){
        if (k >= nt) break;
        int i0 = ti[k], j0 = tj[k];
        atomicAdd(&g_S[(i0+g  )*ZD + j0   + 2*tq    ], d[k][0]);
        atomicAdd(&g_S[(i0+g  )*ZD + j0   + 2*tq + 1], d[k][1]);
        atomicAdd(&g_S[(i0+g+8)*ZD + j0   + 2*tq    ], d[k][2]);
        atomicAdd(&g_S[(i0+g+8)*ZD + j0   + 2*tq + 1], d[k][3]);
        atomicAdd(&g_S[(i0+g  )*ZD + j0+8 + 2*tq    ], d[k][4]);
        atomicAdd(&g_S[(i0+g  )*ZD + j0+8 + 2*tq + 1], d[k][5]);
        atomicAdd(&g_S[(i0+g+8)*ZD + j0+8 + 2*tq    ], d[k][6]);
        atomicAdd(&g_S[(i0+g+8)*ZD + j0+8 + 2*tq + 1], d[k][7]);
    }
    if (tid < ZD) atomicAdd(&g_cs[tid], csacc);
}

// BN stats per output channel (reads upper triangle of S); fold with q
__global__ void k_stats(const float* __restrict__ gamma, const float* __restrict__ beta,
                        const float* __restrict__ q){
    __shared__ float m[ZD], r1[ZD], r2[ZD];
    int ko = blockIdx.x, t = threadIdx.x;
    m[t] = g_M[ko*ZD + t];
    __syncthreads();
    float w = 0.f;
    #pragma unroll 4
    for (int j=0;j<ZD;j++){
        float sv = (j >= t) ? g_S[t*ZD + j] : g_S[j*ZD + t];
        w = fmaf(sv, m[j], w);
    }
    r1[t] = m[t]*w;
    r2[t] = m[t]*g_cs[t];
    __syncthreads();
    for (int s=96; s>=3; s>>=1){
        if (t < s){ r1[t] += r1[t+s]; r2[t] += r2[t+s]; }
        __syncthreads();
    }
    if (t == 0){
        float qf  = r1[0]+r1[1]+r1[2];
        float mz  = (r2[0]+r2[1]+r2[2]) * (1.0f/NV);
        float var = qf*(1.0f/NV) - mz*mz;
        float c   = g_cv[ko];
        float inv = rsqrtf(var + EPS);
        float sc  = gamma[ko]*inv;
        float tsh = beta[ko] - (mz + c)*sc;
        float qk  = q[ko >> 6];
        g_av[ko] = qk*sc;
        g_dt[ko] = qk*(sc*c + tsh);
    }
}

// fuse BN scale + q into V16 (fp16) and dconst
__global__ void k_vk(){
    int idx = blockIdx.x*256 + threadIdx.x;
    if (idx < ZD*OD){
        int i = idx >> 6, o = idx & 63;
        float s = 0.f;
        #pragma unroll
        for (int k=0;k<8;k++){ int ko = k*64+o; s = fmaf(g_av[ko], g_M[ko*ZD + i], s); }
        g_V16[idx] = __float2half(s);
    } else if (idx < ZD*OD + OD){
        int o = idx - ZD*OD;
        float s = 0.f;
        #pragma unroll
        for (int k=0;k<8;k++) s += g_dt[k*64+o];
        g_dc[o] = s;
    }
}

// HMMA out = H @ V^T + dconst ; 128 rows/block, 8 warps (warp w -> rows w*16..+15)
__global__ void __launch_bounds__(256) k_out(float* __restrict__ out){
    __shared__ __align__(16) __half Hs[128*24];   // 16 k-halves + 8 pad per row
    __shared__ __align__(16) __half Vs[16*72];    // 64 o-halves + 8 pad per k-row
    __shared__ float dcs[OD];
    int tid = threadIdx.x, w = tid >> 5, lane = tid & 31;
    int r0 = blockIdx.x * 128;
    int valid = NV - r0; if (valid > 128) valid = 128;
    if (tid < OD) dcs[tid] = g_dc[tid];

    float d[8][4];
    #pragma unroll
    for (int n=0;n<8;n++){
        #pragma unroll
        for (int m=0;m<4;m++) d[n][m] = 0.f;
    }
    unsigned hb = smem_u32(Hs), vb = smem_u32(Vs);
    int aRow = lane & 15, aCol = (lane >> 4) << 3;
    int r8 = lane & 7, mat = lane >> 3;
    int bK = r8 + ((mat & 1) ? 8 : 0);
    int bC = (mat & 2) ? 8 : 0;
    unsigned aaddr = hb + ((unsigned)((w*16 + aRow)*24 + aCol) << 1);

    for (int kc = 0; kc < 12; kc++){
        for (int t = tid; t < 512; t += 256){
            int r = t >> 2, q = t & 3;
            uint2 v = (r < valid) ? __ldg(&g_H16[(size_t)(r0+r)*48 + kc*4 + q])
                                  : make_uint2(0u,0u);
            *(uint2*)&Hs[r*24 + q*4] = v;
        }
        {
            int r = tid >> 4, q = tid & 15;
            uint2 v = *(const uint2*)&g_V16[(kc*16 + r)*64 + q*4];
            *(uint2*)&Vs[r*72 + q*4] = v;
        }
        __syncthreads();
        unsigned a0,a1,a2,a3;
        asm volatile("ldmatrix.sync.aligned.m8n8.x4.shared.b16 {%0,%1,%2,%3}, [%4];"
            : "=r"(a0),"=r"(a1),"=r"(a2),"=r"(a3) : "r"(aaddr));
        #pragma unroll
        for (int jb = 0; jb < 4; jb++){
            unsigned baddr = vb + ((unsigned)(bK*72 + jb*16 + bC) << 1);
            unsigned b0,b1,b2,b3;
            asm volatile("ldmatrix.sync.aligned.m8n8.x4.trans.shared.b16 {%0,%1,%2,%3}, [%4];"
                : "=r"(b0),"=r"(b1),"=r"(b2),"=r"(b3) : "r"(baddr));
            asm volatile("mma.sync.aligned.m16n8k16.row.col.f32.f16.f16.f32 "
                "{%0,%1,%2,%3}, {%4,%5,%6,%7}, {%8,%9}, {%0,%1,%2,%3};"
                : "+f"(d[jb*2][0]),"+f"(d[jb*2][1]),"+f"(d[jb*2][2]),"+f"(d[jb*2][3])
                : "r"(a0),"r"(a1),"r"(a2),"r"(a3), "r"(b0),"r"(b1));
            asm volatile("mma.sync.aligned.m16n8k16.row.col.f32.f16.f16.f32 "
                "{%0,%1,%2,%3}, {%4,%5,%6,%7}, {%8,%9}, {%0,%1,%2,%3};"
                : "+f"(d[jb*2+1][0]),"+f"(d[jb*2+1][1]),"+f"(d[jb*2+1][2]),"+f"(d[jb*2+1][3])
                : "r"(a0),"r"(a1),"r"(a2),"r"(a3), "r"(b2),"r"(b3));
        }
        __syncthreads();
    }
    int g = lane >> 2, tq = lane & 3;
    #pragma unroll
    for (int n = 0; n < 8; n++){
        int col = (n >> 1)*16 + (n & 1)*8 + 2*tq;
        int row = r0 + w*16 + g;
        if (row < NV){
            float2 p = make_float2(d[n][0] + dcs[col], d[n][1] + dcs[col+1]);
            *(float2*)&out[(size_t)row*64 + col] = p;
        }
        row += 8;
        if (row < NV){
            float2 p = make_float2(d[n][2] + dcs[col], d[n][3] + dcs[col+1]);
            *(float2*)&out[(size_t)row*64 + col] = p;
        }
    }
}

extern "C" void kernel_launch(void* const* d_in, const int* in_sizes, int n_in,
                              void* d_out, int out_size){
    const float* feats = (const float*)d_in[0];
    const int*   src   = (const int*)  d_in[1];
    const int*   dst   = (const int*)  d_in[2];
    const float* W0    = (const float*)d_in[3];
    const float* b0    = (const float*)d_in[4];
    const float* W1    = (const float*)d_in[5];
    const float* b1    = (const float*)d_in[6];
    const float* W2    = (const float*)d_in[7];
    const float* b2    = (const float*)d_in[8];
    const float* fcW   = (const float*)d_in[9];
    const float* fcb   = (const float*)d_in[10];
    const float* gamma = (const float*)d_in[11];
    const float* beta  = (const float*)d_in[12];
    const float* q     = (const float*)d_in[13];
    float* out = (float*)d_out;

    k_zero   <<<9375, 256>>>();                                   // #1
    k_deg    <<<6250, 256>>>(dst);                                // #2
    k_scan1  <<<98, 1024>>>();                                    // #3
    k_wgemm  <<<192, 256>>>(fcW, W0, W1, W2);                     // #4
    k_wbias  <<<64, 256>>>(fcW, b0, b1, b2, fcb);                 // #5
    k_scan3t0<<<391, 256>>>(feats);                               // #6
    k_place  <<<6250, 256>>>(src, dst);                           // #7
    k_hop    <<<12500, 256>>>(0, 0,  1);                          // #8
    k_hop    <<<12500, 256>>>(1, 16, 1);                          // #9
    k_hop    <<<12500, 256>>>(0, 32, 0);                          // #10
    k_gram   <<<148, 512>>>();                                    // #11
    k_stats  <<<512, 192>>>(gamma, beta, q);                      // #12
    k_vk     <<<49, 256>>>();                                     // #13
    k_out    <<<782, 256>>>(out);                                 // #14
}